// round 1
// baseline (speedup 1.0000x reference)
#include <cuda_runtime.h>
#include <cuda_bf16.h>
#include <cstdint>

// ---------------------------------------------------------------------------
// Problem constants
// ---------------------------------------------------------------------------
#define D_MODEL 768
#define SEQ     2048
#define NHEADS  12
#define DH      64

// Scratch buffers (allocation-free rule: __device__ globals)
// sized for B=2, S=2048 -> M = 4096 rows
#define MROWS (2 * SEQ)
__device__ float g_q[MROWS * D_MODEL];
__device__ float g_k[MROWS * D_MODEL];
__device__ float g_v[MROWS * D_MODEL];
__device__ float g_att[MROWS * D_MODEL];
__device__ float g_x[MROWS * D_MODEL];

// ---------------------------------------------------------------------------
// Generic NT SGEMM:  C[m,n] = sum_k A[m,k] * W[n,k] + bias[n] (+ R[m,n])
// A: [M,K] row-major, W: [N,K] row-major (torch Linear weight)
// Tiles: BM=BN=64, BK=16, 256 threads, 4x4 micro-tile per thread.
// ---------------------------------------------------------------------------
#define BM 64
#define BN 64
#define BK 16
#define SPAD 68   // smem row stride (floats); 68*4 bytes = 16B-aligned rows

__global__ __launch_bounds__(256) void gemm_nt(
    const float* __restrict__ A, const float* __restrict__ W,
    const float* __restrict__ bias, const float* __restrict__ R,
    float* __restrict__ C, int M, int N, int K)
{
    __shared__ float As[BK][SPAD];
    __shared__ float Ws[BK][SPAD];

    const int tid = threadIdx.x;
    const int tx = tid & 15;
    const int ty = tid >> 4;
    const int bm = blockIdx.y * BM;
    const int bn = blockIdx.x * BN;

    // load indices: each thread loads one float4 of A and one of W per BK tile
    const int lr = tid >> 2;        // 0..63 : row within tile
    const int lk = (tid & 3) * 4;   // 0,4,8,12 : k offset

    const float* Ap = A + (size_t)(bm + lr) * K + lk;
    const float* Wp = W + (size_t)(bn + lr) * K + lk;

    float acc[4][4];
#pragma unroll
    for (int i = 0; i < 4; i++)
#pragma unroll
        for (int j = 0; j < 4; j++) acc[i][j] = 0.f;

    for (int k0 = 0; k0 < K; k0 += BK) {
        float4 a4 = *(const float4*)(Ap + k0);
        float4 w4 = *(const float4*)(Wp + k0);
        As[lk + 0][lr] = a4.x; As[lk + 1][lr] = a4.y;
        As[lk + 2][lr] = a4.z; As[lk + 3][lr] = a4.w;
        Ws[lk + 0][lr] = w4.x; Ws[lk + 1][lr] = w4.y;
        Ws[lk + 2][lr] = w4.z; Ws[lk + 3][lr] = w4.w;
        __syncthreads();

#pragma unroll
        for (int k = 0; k < BK; k++) {
            float4 a = *(const float4*)&As[k][ty * 4];
            float4 w = *(const float4*)&Ws[k][tx * 4];
            float av[4] = {a.x, a.y, a.z, a.w};
            float wv[4] = {w.x, w.y, w.z, w.w};
#pragma unroll
            for (int i = 0; i < 4; i++)
#pragma unroll
                for (int j = 0; j < 4; j++) acc[i][j] += av[i] * wv[j];
        }
        __syncthreads();
    }

#pragma unroll
    for (int i = 0; i < 4; i++) {
        const int row = bm + ty * 4 + i;
#pragma unroll
        for (int j = 0; j < 4; j++) {
            const int col = bn + tx * 4 + j;
            float v = acc[i][j] + bias[col];
            if (R) v += R[(size_t)row * N + col];
            C[(size_t)row * N + col] = v;
        }
    }
}

// ---------------------------------------------------------------------------
// Flash-attention (fp32, online softmax).
// CTA: one (batch, head, 64-query block). 256 threads, 4x4 micro-tiles.
// smem: Qs[d][m] (transposed), KPs: K as [d][n] then P as [n][m], Vs[n][d].
// ---------------------------------------------------------------------------
#define BQ 64
#define BKV 64
#define ATTN_SMEM (3 * 64 * SPAD * 4)   // 52224 bytes

__global__ __launch_bounds__(256) void attn_kernel(
    const float* __restrict__ gq, const float* __restrict__ gk,
    const float* __restrict__ gv, float* __restrict__ gout, int S)
{
    extern __shared__ float sm[];
    float* Qs  = sm;                 // [64][SPAD]  Qs[d*SPAD + m]
    float* KPs = sm + 64 * SPAD;     // [64][SPAD]  K: [d][n], later P: [n][m]
    float* Vs  = sm + 2 * 64 * SPAD; // [64][SPAD]  Vs[n*SPAD + d]

    const int tid = threadIdx.x;
    const int tx = tid & 15;
    const int ty = tid >> 4;
    const int qb = blockIdx.x * BQ;
    const int h  = blockIdx.y;
    const int b  = blockIdx.z;
    const size_t base = ((size_t)b * S) * D_MODEL + h * DH;

    // Load Q block transposed: Qs[d][m]
#pragma unroll
    for (int it = 0; it < 16; it++) {
        int idx = tid + it * 256;
        int m = idx >> 6, d = idx & 63;
        Qs[d * SPAD + m] = gq[base + (size_t)(qb + m) * D_MODEL + d];
    }

    float mi[4], li[4], o[4][4];
#pragma unroll
    for (int i = 0; i < 4; i++) {
        mi[i] = -1e30f; li[i] = 0.f;
#pragma unroll
        for (int j = 0; j < 4; j++) o[i][j] = 0.f;
    }
    __syncthreads();

    for (int kv = 0; kv < S; kv += BKV) {
        // load K (transposed) and V
#pragma unroll
        for (int it = 0; it < 16; it++) {
            int idx = tid + it * 256;
            int n = idx >> 6, d = idx & 63;
            float kvval = gk[base + (size_t)(kv + n) * D_MODEL + d];
            float vvval = gv[base + (size_t)(kv + n) * D_MODEL + d];
            KPs[d * SPAD + n] = kvval;
            Vs[n * SPAD + d]  = vvval;
        }
        __syncthreads();

        // S = Q K^T  (64q x 64k, inner dh=64)
        float s[4][4];
#pragma unroll
        for (int i = 0; i < 4; i++)
#pragma unroll
            for (int j = 0; j < 4; j++) s[i][j] = 0.f;

#pragma unroll 8
        for (int d = 0; d < DH; d++) {
            float4 a = *(const float4*)&Qs[d * SPAD + ty * 4];
            float4 w = *(const float4*)&KPs[d * SPAD + tx * 4];
            float av[4] = {a.x, a.y, a.z, a.w};
            float wv[4] = {w.x, w.y, w.z, w.w};
#pragma unroll
            for (int i = 0; i < 4; i++)
#pragma unroll
                for (int j = 0; j < 4; j++) s[i][j] += av[i] * wv[j];
        }

        // Online softmax per q-row. Rows of a given ty are owned by 16
        // consecutive lanes (tx = 0..15) -> shfl_xor over 8,4,2,1.
#pragma unroll
        for (int i = 0; i < 4; i++) {
            float rm = -1e30f;
#pragma unroll
            for (int j = 0; j < 4; j++) {
                s[i][j] *= 0.125f;  // 1/sqrt(64)
                rm = fmaxf(rm, s[i][j]);
            }
#pragma unroll
            for (int off = 8; off; off >>= 1)
                rm = fmaxf(rm, __shfl_xor_sync(0xffffffffu, rm, off));
            float mn = fmaxf(mi[i], rm);
            float corr = __expf(mi[i] - mn);
            float rsum = 0.f;
#pragma unroll
            for (int j = 0; j < 4; j++) {
                float p = __expf(s[i][j] - mn);
                s[i][j] = p;
                rsum += p;
            }
#pragma unroll
            for (int off = 8; off; off >>= 1)
                rsum += __shfl_xor_sync(0xffffffffu, rsum, off);
            li[i] = li[i] * corr + rsum;
            mi[i] = mn;
#pragma unroll
            for (int j = 0; j < 4; j++) o[i][j] *= corr;
        }

        __syncthreads();  // everyone done reading K tile
        // write P transposed into K's smem: Ps[n][m]
#pragma unroll
        for (int i = 0; i < 4; i++)
#pragma unroll
            for (int j = 0; j < 4; j++)
                KPs[(tx * 4 + j) * SPAD + ty * 4 + i] = s[i][j];
        __syncthreads();

        // O += P V  (64q x 64d, inner n=64)
#pragma unroll 8
        for (int n = 0; n < BKV; n++) {
            float4 p = *(const float4*)&KPs[n * SPAD + ty * 4];
            float4 vv = *(const float4*)&Vs[n * SPAD + tx * 4];
            float pv[4] = {p.x, p.y, p.z, p.w};
            float vw[4] = {vv.x, vv.y, vv.z, vv.w};
#pragma unroll
            for (int i = 0; i < 4; i++)
#pragma unroll
                for (int j = 0; j < 4; j++) o[i][j] += pv[i] * vw[j];
        }
        __syncthreads();  // before next iteration overwrites KPs / Vs
    }

#pragma unroll
    for (int i = 0; i < 4; i++) {
        float inv = 1.f / li[i];
#pragma unroll
        for (int j = 0; j < 4; j++)
            gout[base + (size_t)(qb + ty * 4 + i) * D_MODEL + tx * 4 + j] =
                o[i][j] * inv;
    }
}

// ---------------------------------------------------------------------------
// LayerNorm over last dim (768). One CTA per row, 256 threads x 3 elems.
// ---------------------------------------------------------------------------
__global__ __launch_bounds__(256) void ln_kernel(
    const float* __restrict__ x, const float* __restrict__ gamma,
    const float* __restrict__ beta, float* __restrict__ out)
{
    const int row = blockIdx.x;
    const float* xr = x + (size_t)row * D_MODEL;
    const int tid = threadIdx.x;

    float v[3];
    float s = 0.f, s2 = 0.f;
#pragma unroll
    for (int i = 0; i < 3; i++) {
        v[i] = xr[tid + i * 256];
        s += v[i];
        s2 += v[i] * v[i];
    }
#pragma unroll
    for (int off = 16; off; off >>= 1) {
        s  += __shfl_xor_sync(0xffffffffu, s,  off);
        s2 += __shfl_xor_sync(0xffffffffu, s2, off);
    }
    __shared__ float rs[8], rs2[8];
    __shared__ float mu_s, rstd_s;
    const int w = tid >> 5;
    if ((tid & 31) == 0) { rs[w] = s; rs2[w] = s2; }
    __syncthreads();
    if (tid == 0) {
        float a = 0.f, bq = 0.f;
#pragma unroll
        for (int i = 0; i < 8; i++) { a += rs[i]; bq += rs2[i]; }
        float mu = a * (1.f / D_MODEL);
        float var = bq * (1.f / D_MODEL) - mu * mu;
        mu_s = mu;
        rstd_s = rsqrtf(var + 1e-5f);
    }
    __syncthreads();
    const float mu = mu_s, rstd = rstd_s;
#pragma unroll
    for (int i = 0; i < 3; i++) {
        int c = tid + i * 256;
        out[(size_t)row * D_MODEL + c] = (v[i] - mu) * rstd * gamma[c] + beta[c];
    }
}

// ---------------------------------------------------------------------------
// kernel_launch
// Inputs (metadata order): Q, W_q, b_q, W_k, b_k, W_v, b_v, W_o, b_o,
//                          ln_gamma, ln_beta
// ---------------------------------------------------------------------------
extern "C" void kernel_launch(void* const* d_in, const int* in_sizes, int n_in,
                              void* d_out, int out_size)
{
    const float* Q     = (const float*)d_in[0];
    const float* Wq    = (const float*)d_in[1];
    const float* bq    = (const float*)d_in[2];
    const float* Wk    = (const float*)d_in[3];
    const float* bk    = (const float*)d_in[4];
    const float* Wv    = (const float*)d_in[5];
    const float* bv    = (const float*)d_in[6];
    const float* Wo    = (const float*)d_in[7];
    const float* bo    = (const float*)d_in[8];
    const float* gamma = (const float*)d_in[9];
    const float* beta  = (const float*)d_in[10];
    float* out = (float*)d_out;

    const int M = in_sizes[0] / D_MODEL;  // B * S = 4096
    const int S = SEQ;
    const int B = M / S;

    float *q, *k, *v, *att, *x;
    cudaGetSymbolAddress((void**)&q,   g_q);
    cudaGetSymbolAddress((void**)&k,   g_k);
    cudaGetSymbolAddress((void**)&v,   g_v);
    cudaGetSymbolAddress((void**)&att, g_att);
    cudaGetSymbolAddress((void**)&x,   g_x);

    dim3 gg(D_MODEL / BN, M / BM);

    gemm_nt<<<gg, 256>>>(Q, Wq, bq, nullptr, q, M, D_MODEL, D_MODEL);
    gemm_nt<<<gg, 256>>>(Q, Wk, bk, nullptr, k, M, D_MODEL, D_MODEL);
    gemm_nt<<<gg, 256>>>(Q, Wv, bv, nullptr, v, M, D_MODEL, D_MODEL);

    cudaFuncSetAttribute((const void*)attn_kernel,
                         cudaFuncAttributeMaxDynamicSharedMemorySize, ATTN_SMEM);
    attn_kernel<<<dim3(S / BQ, NHEADS, B), 256, ATTN_SMEM>>>(q, k, v, att, S);

    // O-projection + residual
    gemm_nt<<<gg, 256>>>(att, Wo, bo, Q, x, M, D_MODEL, D_MODEL);

    ln_kernel<<<M, 256>>>(x, gamma, beta, out);
}

// round 3
// speedup vs baseline: 1.9196x; 1.9196x over previous
#include <cuda_runtime.h>
#include <cuda_bf16.h>
#include <cstdint>

// ---------------------------------------------------------------------------
// Problem constants
// ---------------------------------------------------------------------------
#define D_MODEL 768
#define SEQ     2048
#define NHEADS  12
#define DH      64
#define MROWS   (2 * SEQ)

// Scratch (allocation-free rule: __device__ globals)
__device__ float g_q[MROWS * D_MODEL];
__device__ float g_k[MROWS * D_MODEL];
__device__ float g_v[MROWS * D_MODEL];
__device__ float g_att[MROWS * D_MODEL];
__device__ float g_x[MROWS * D_MODEL];

// ---------------------------------------------------------------------------
// Warp-MMA helpers (sm_80+ PTX: mma.sync + ldmatrix; compiles for sm_100)
// ---------------------------------------------------------------------------
__device__ __forceinline__ uint32_t smem_u32(const void* p) {
    uint32_t a;
    asm("{ .reg .u64 t; cvta.to.shared.u64 t, %1; cvt.u32.u64 %0, t; }"
        : "=r"(a) : "l"(p));
    return a;
}

#define MMA_BF16(d, a, b) \
    asm volatile("mma.sync.aligned.m16n8k16.row.col.f32.bf16.bf16.f32 " \
        "{%0,%1,%2,%3}, {%4,%5,%6,%7}, {%8,%9}, {%0,%1,%2,%3};" \
        : "+f"((d)[0]), "+f"((d)[1]), "+f"((d)[2]), "+f"((d)[3]) \
        : "r"((a)[0]), "r"((a)[1]), "r"((a)[2]), "r"((a)[3]), \
          "r"((b)[0]), "r"((b)[1]))

#define LDSM4(r, addr) \
    asm volatile("ldmatrix.sync.aligned.m8n8.x4.shared.b16 {%0,%1,%2,%3}, [%4];" \
        : "=r"((r)[0]), "=r"((r)[1]), "=r"((r)[2]), "=r"((r)[3]) : "r"(addr))

#define LDSM4T(r, addr) \
    asm volatile("ldmatrix.sync.aligned.m8n8.x4.trans.shared.b16 {%0,%1,%2,%3}, [%4];" \
        : "=r"((r)[0]), "=r"((r)[1]), "=r"((r)[2]), "=r"((r)[3]) : "r"(addr))

// split (x,y) fp32 -> packed bf16 hi pair (lo16=x) and lo pair (residual)
__device__ __forceinline__ void cvt_hilo(float x, float y, uint32_t& h2, uint32_t& l2) {
    uint32_t h;
    asm("cvt.rn.bf16x2.f32 %0, %1, %2;" : "=r"(h) : "f"(y), "f"(x));
    float hx = __uint_as_float(h << 16);
    float hy = __uint_as_float(h & 0xffff0000u);
    uint32_t l;
    float lx = x - hx, ly = y - hy;
    asm("cvt.rn.bf16x2.f32 %0, %1, %2;" : "=r"(l) : "f"(ly), "f"(lx));
    h2 = h; l2 = l;
}

// load N4 float4s from src, scale, split, store bf16 pairs into hi/lo smem
// at byte offset row*STRIDE + (colb + i*4)*2
template <int STRIDE, int N4>
__device__ __forceinline__ void conv_row(const float* __restrict__ src,
                                         char* hi, char* lo,
                                         int row, int colb, float scale) {
    char* hp = hi + row * STRIDE + colb * 2;
    char* lp = lo + row * STRIDE + colb * 2;
#pragma unroll
    for (int i = 0; i < N4; i++) {
        float4 v = *(const float4*)(src + i * 4);
        v.x *= scale; v.y *= scale; v.z *= scale; v.w *= scale;
        uint32_t h0, l0, h1, l1;
        cvt_hilo(v.x, v.y, h0, l0);
        cvt_hilo(v.z, v.w, h1, l1);
        *(uint32_t*)(hp + i * 8)     = h0;
        *(uint32_t*)(hp + i * 8 + 4) = h1;
        *(uint32_t*)(lp + i * 8)     = l0;
        *(uint32_t*)(lp + i * 8 + 4) = l1;
    }
}

// ---------------------------------------------------------------------------
// GEMM:  C[m,n] = sum_k A[m,k]*W[n,k] + bias[n] (+ R[m,n])
// CTA tile 128x128, BK=32, 8 warps (4m x 2n), warp tile 32x64.
// bf16 hi/lo x3 mma emulation of fp32.
// ---------------------------------------------------------------------------
#define G_STRIDE 80   // 40 bf16 per row (32 + 8 pad) -> conflict-free ldmatrix

__global__ __launch_bounds__(256) void gemm_wm(
    const float* __restrict__ A, const float* __restrict__ W,
    const float* __restrict__ bias, const float* __restrict__ R,
    float* __restrict__ C, int M, int N, int K)
{
    __shared__ __align__(16) char sAhi[128 * G_STRIDE];
    __shared__ __align__(16) char sAlo[128 * G_STRIDE];
    __shared__ __align__(16) char sBhi[128 * G_STRIDE];
    __shared__ __align__(16) char sBlo[128 * G_STRIDE];

    const int tid = threadIdx.x;
    const int lane = tid & 31;
    const int warp = tid >> 5;
    const int wm = warp >> 1;
    const int wn = warp & 1;
    const int bm = blockIdx.y * 128;
    const int bn = blockIdx.x * 128;

    const uint32_t uAhi = smem_u32(sAhi), uAlo = smem_u32(sAlo);
    const uint32_t uBhi = smem_u32(sBhi), uBlo = smem_u32(sBlo);

    float acc[2][8][4];
#pragma unroll
    for (int mt = 0; mt < 2; mt++)
#pragma unroll
        for (int nt = 0; nt < 8; nt++)
#pragma unroll
            for (int c = 0; c < 4; c++) acc[mt][nt][c] = 0.f;

    const int lrow = tid >> 1;
    const int lcb = (tid & 1) * 16;

    for (int kt = 0; kt < K / 32; kt++) {
        conv_row<G_STRIDE, 4>(A + (size_t)(bm + lrow) * K + kt * 32 + lcb,
                              sAhi, sAlo, lrow, lcb, 1.0f);
        conv_row<G_STRIDE, 4>(W + (size_t)(bn + lrow) * K + kt * 32 + lcb,
                              sBhi, sBlo, lrow, lcb, 1.0f);
        __syncthreads();

#pragma unroll
        for (int ks = 0; ks < 2; ks++) {
            uint32_t ah[2][4], al[2][4];
#pragma unroll
            for (int mt = 0; mt < 2; mt++) {
                uint32_t off = (uint32_t)(wm * 32 + mt * 16 + (lane & 15)) * G_STRIDE
                             + (uint32_t)(ks * 16 + (lane >> 4) * 8) * 2;
                LDSM4(ah[mt], uAhi + off);
                LDSM4(al[mt], uAlo + off);
            }
            uint32_t bh[8][2], bl[8][2];
            {
                const int g = lane >> 3;
                const int nr = wn * 64 + (lane & 7) + ((g & 2) ? 8 : 0);
                const int kf = ks * 16 + (g & 1) * 8;
#pragma unroll
                for (int np = 0; np < 4; np++) {
                    uint32_t off = (uint32_t)(nr + np * 16) * G_STRIDE + (uint32_t)kf * 2;
                    LDSM4(&bh[np * 2][0], uBhi + off);
                    LDSM4(&bl[np * 2][0], uBlo + off);
                }
            }
#pragma unroll
            for (int mt = 0; mt < 2; mt++)
#pragma unroll
                for (int nt = 0; nt < 8; nt++) {
                    MMA_BF16(acc[mt][nt], ah[mt], bh[nt]);
                    MMA_BF16(acc[mt][nt], ah[mt], bl[nt]);
                    MMA_BF16(acc[mt][nt], al[mt], bh[nt]);
                }
        }
        __syncthreads();
    }

    // epilogue
#pragma unroll
    for (int mt = 0; mt < 2; mt++)
#pragma unroll
        for (int h = 0; h < 2; h++) {
            const int row = bm + wm * 32 + mt * 16 + (lane >> 2) + h * 8;
#pragma unroll
            for (int nt = 0; nt < 8; nt++) {
                const int col = bn + wn * 64 + nt * 8 + (lane & 3) * 2;
                float2 v;
                v.x = acc[mt][nt][2 * h]     + bias[col];
                v.y = acc[mt][nt][2 * h + 1] + bias[col + 1];
                if (R) {
                    const float2 rr = *(const float2*)(R + (size_t)row * N + col);
                    v.x += rr.x; v.y += rr.y;
                }
                *(float2*)(C + (size_t)row * N + col) = v;
            }
        }
}

// ---------------------------------------------------------------------------
// Flash attention via warp mma, bf16 hi/lo x3 precision.
// CTA = (128 q-rows, head, batch); 8 warps (4m x 2 key-halves); 16 kv iters.
// ---------------------------------------------------------------------------
#define A_STRIDE 144   // 72 bf16 per row (64 + 8 pad)
#define AT_RED 0                       // redm[2][128], reds[2][128] = 2048
#define AT_Q   2048
#define AT_QLO (AT_Q   + 18432)
#define AT_K   (AT_QLO + 18432)        // 38912 (reused as O staging at end)
#define AT_KLO (AT_K   + 18432)
#define AT_V   (AT_KLO + 18432)
#define AT_VLO (AT_V   + 18432)
#define AT_SMEM (AT_VLO + 18432)       // 112640

__global__ __launch_bounds__(256) void attn_wm(
    const float* __restrict__ gq, const float* __restrict__ gk,
    const float* __restrict__ gv, float* __restrict__ gout)
{
    extern __shared__ char sm[];
    const int tid = threadIdx.x;
    const int lane = tid & 31;
    const int warp = tid >> 5;
    const int wm = warp >> 1;      // q-row quarter
    const int wn = warp & 1;       // key half (0: keys 0-63, 1: 64-127)
    const int qb = blockIdx.x * 128;
    const int h = blockIdx.y;
    const int b = blockIdx.z;
    const size_t base = ((size_t)b * SEQ) * D_MODEL + (size_t)h * DH;

    float* redm = (float*)(sm + AT_RED);       // [2][128]
    float* reds = redm + 256;                  // [2][128]

    const uint32_t uQhi = smem_u32(sm + AT_Q),  uQlo = smem_u32(sm + AT_QLO);
    const uint32_t uKhi = smem_u32(sm + AT_K),  uKlo = smem_u32(sm + AT_KLO);
    const uint32_t uVhi = smem_u32(sm + AT_V),  uVlo = smem_u32(sm + AT_VLO);

    const int lrow = tid >> 1;
    const int lcb = (tid & 1) * 32;

    // Q tile once, scaled by 1/sqrt(dh)
    conv_row<A_STRIDE, 8>(gq + base + (size_t)(qb + lrow) * D_MODEL + lcb,
                          sm + AT_Q, sm + AT_QLO, lrow, lcb, 0.125f);

    float o[2][8][4];
    float m_run[2][2], l_run[2][2];
#pragma unroll
    for (int mt = 0; mt < 2; mt++) {
#pragma unroll
        for (int hh = 0; hh < 2; hh++) { m_run[mt][hh] = -1e30f; l_run[mt][hh] = 0.f; }
#pragma unroll
        for (int nt = 0; nt < 8; nt++)
#pragma unroll
            for (int c = 0; c < 4; c++) o[mt][nt][c] = 0.f;
    }

    for (int it = 0; it < 16; it++) {
        const int kv = it * 128;
        conv_row<A_STRIDE, 8>(gk + base + (size_t)(kv + lrow) * D_MODEL + lcb,
                              sm + AT_K, sm + AT_KLO, lrow, lcb, 1.0f);
        conv_row<A_STRIDE, 8>(gv + base + (size_t)(kv + lrow) * D_MODEL + lcb,
                              sm + AT_V, sm + AT_VLO, lrow, lcb, 1.0f);
        __syncthreads();

        // ---- S = Q K^T (warp: 32 q x 64 keys), K-dim = dh = 64 ----
        float s[2][8][4];
#pragma unroll
        for (int mt = 0; mt < 2; mt++)
#pragma unroll
            for (int nt = 0; nt < 8; nt++)
#pragma unroll
                for (int c = 0; c < 4; c++) s[mt][nt][c] = 0.f;

#pragma unroll
        for (int ks = 0; ks < 4; ks++) {
            uint32_t ah[2][4], al[2][4];
#pragma unroll
            for (int mt = 0; mt < 2; mt++) {
                uint32_t off = (uint32_t)(wm * 32 + mt * 16 + (lane & 15)) * A_STRIDE
                             + (uint32_t)(ks * 16 + (lane >> 4) * 8) * 2;
                LDSM4(ah[mt], uQhi + off);
                LDSM4(al[mt], uQlo + off);
            }
            uint32_t bh[8][2], bl[8][2];
            {
                const int g = lane >> 3;
                const int nr = wn * 64 + (lane & 7) + ((g & 2) ? 8 : 0);
                const int kf = ks * 16 + (g & 1) * 8;
#pragma unroll
                for (int np = 0; np < 4; np++) {
                    uint32_t off = (uint32_t)(nr + np * 16) * A_STRIDE + (uint32_t)kf * 2;
                    LDSM4(&bh[np * 2][0], uKhi + off);
                    LDSM4(&bl[np * 2][0], uKlo + off);
                }
            }
#pragma unroll
            for (int mt = 0; mt < 2; mt++)
#pragma unroll
                for (int nt = 0; nt < 8; nt++) {
                    MMA_BF16(s[mt][nt], ah[mt], bh[nt]);
                    MMA_BF16(s[mt][nt], ah[mt], bl[nt]);
                    MMA_BF16(s[mt][nt], al[mt], bh[nt]);
                }
        }

        // ---- online softmax ----
        float pm[2][2];
#pragma unroll
        for (int mt = 0; mt < 2; mt++)
#pragma unroll
            for (int hh = 0; hh < 2; hh++) {
                float m = -1e30f;
#pragma unroll
                for (int nt = 0; nt < 8; nt++)
                    m = fmaxf(m, fmaxf(s[mt][nt][2 * hh], s[mt][nt][2 * hh + 1]));
                m = fmaxf(m, __shfl_xor_sync(0xffffffffu, m, 1));
                m = fmaxf(m, __shfl_xor_sync(0xffffffffu, m, 2));
                pm[mt][hh] = m;
            }
        if ((lane & 3) == 0) {
#pragma unroll
            for (int mt = 0; mt < 2; mt++)
#pragma unroll
                for (int hh = 0; hh < 2; hh++)
                    redm[wn * 128 + wm * 32 + mt * 16 + (lane >> 2) + hh * 8] = pm[mt][hh];
        }
        __syncthreads();

        float corr[2][2];
#pragma unroll
        for (int mt = 0; mt < 2; mt++)
#pragma unroll
            for (int hh = 0; hh < 2; hh++) {
                const int row = wm * 32 + mt * 16 + (lane >> 2) + hh * 8;
                const float m_new = fmaxf(m_run[mt][hh],
                                          fmaxf(redm[row], redm[128 + row]));
                corr[mt][hh] = __expf(m_run[mt][hh] - m_new);
                m_run[mt][hh] = m_new;
            }

        float ps[2][2] = {{0.f, 0.f}, {0.f, 0.f}};
#pragma unroll
        for (int mt = 0; mt < 2; mt++)
#pragma unroll
            for (int nt = 0; nt < 8; nt++)
#pragma unroll
                for (int c = 0; c < 4; c++) {
                    const int hh = c >> 1;
                    const float p = __expf(s[mt][nt][c] - m_run[mt][hh]);
                    s[mt][nt][c] = p;
                    ps[mt][hh] += p;
                }
#pragma unroll
        for (int mt = 0; mt < 2; mt++)
#pragma unroll
            for (int hh = 0; hh < 2; hh++) {
                float v = ps[mt][hh];
                v += __shfl_xor_sync(0xffffffffu, v, 1);
                v += __shfl_xor_sync(0xffffffffu, v, 2);
                ps[mt][hh] = v;
            }
        if ((lane & 3) == 0) {
#pragma unroll
            for (int mt = 0; mt < 2; mt++)
#pragma unroll
                for (int hh = 0; hh < 2; hh++)
                    reds[wn * 128 + wm * 32 + mt * 16 + (lane >> 2) + hh * 8] = ps[mt][hh];
        }
        __syncthreads();
#pragma unroll
        for (int mt = 0; mt < 2; mt++)
#pragma unroll
            for (int hh = 0; hh < 2; hh++) {
                const int row = wm * 32 + mt * 16 + (lane >> 2) + hh * 8;
                l_run[mt][hh] = l_run[mt][hh] * corr[mt][hh]
                              + reds[row] + reds[128 + row];
            }

        // rescale O
#pragma unroll
        for (int mt = 0; mt < 2; mt++)
#pragma unroll
            for (int nt = 0; nt < 8; nt++)
#pragma unroll
                for (int c = 0; c < 4; c++) o[mt][nt][c] *= corr[mt][c >> 1];

        // ---- O += P V (register-resident P, per 16-key chunk) ----
#pragma unroll
        for (int kc = 0; kc < 4; kc++) {
            uint32_t ph[2][4], pl[2][4];
#pragma unroll
            for (int mt = 0; mt < 2; mt++) {
                cvt_hilo(s[mt][2 * kc][0],     s[mt][2 * kc][1],     ph[mt][0], pl[mt][0]);
                cvt_hilo(s[mt][2 * kc][2],     s[mt][2 * kc][3],     ph[mt][1], pl[mt][1]);
                cvt_hilo(s[mt][2 * kc + 1][0], s[mt][2 * kc + 1][1], ph[mt][2], pl[mt][2]);
                cvt_hilo(s[mt][2 * kc + 1][2], s[mt][2 * kc + 1][3], ph[mt][3], pl[mt][3]);
            }
            uint32_t vh[8][2], vl[8][2];
            {
                const int g = lane >> 3;
                const int kr = wn * 64 + kc * 16 + (lane & 7) + ((g & 1) ? 8 : 0);
                const int nf = ((g & 2) ? 8 : 0);
#pragma unroll
                for (int np = 0; np < 4; np++) {
                    uint32_t off = (uint32_t)kr * A_STRIDE
                                 + (uint32_t)(np * 16 + nf) * 2;
                    LDSM4T(&vh[np * 2][0], uVhi + off);
                    LDSM4T(&vl[np * 2][0], uVlo + off);
                }
            }
#pragma unroll
            for (int mt = 0; mt < 2; mt++)
#pragma unroll
                for (int nt = 0; nt < 8; nt++) {
                    MMA_BF16(o[mt][nt], ph[mt], vh[nt]);
                    MMA_BF16(o[mt][nt], ph[mt], vl[nt]);
                    MMA_BF16(o[mt][nt], pl[mt], vh[nt]);
                }
        }
        __syncthreads();   // protect K/V smem before next iteration's load
    }

    // ---- combine the two key-half partials and store ----
    float* stg = (float*)(sm + AT_K);           // reuse K region (34 KB)
    const int sidx = (wm * 32 + lane) * 68;
    if (wn == 1) {
#pragma unroll
        for (int mt = 0; mt < 2; mt++)
#pragma unroll
            for (int nt = 0; nt < 8; nt++)
                *(float4*)&stg[sidx + (mt * 8 + nt) * 4] =
                    make_float4(o[mt][nt][0], o[mt][nt][1], o[mt][nt][2], o[mt][nt][3]);
    }
    __syncthreads();
    if (wn == 0) {
#pragma unroll
        for (int mt = 0; mt < 2; mt++) {
            float inv0 = 1.f / l_run[mt][0];
            float inv1 = 1.f / l_run[mt][1];
#pragma unroll
            for (int nt = 0; nt < 8; nt++) {
                float4 p = *(float4*)&stg[sidx + (mt * 8 + nt) * 4];
                const int col = nt * 8 + (lane & 3) * 2;
                const int r0 = qb + wm * 32 + mt * 16 + (lane >> 2);
                float2 v0, v1;
                v0.x = (o[mt][nt][0] + p.x) * inv0;
                v0.y = (o[mt][nt][1] + p.y) * inv0;
                v1.x = (o[mt][nt][2] + p.z) * inv1;
                v1.y = (o[mt][nt][3] + p.w) * inv1;
                *(float2*)(gout + base + (size_t)r0 * D_MODEL + col) = v0;
                *(float2*)(gout + base + (size_t)(r0 + 8) * D_MODEL + col) = v1;
            }
        }
    }
}

// ---------------------------------------------------------------------------
// LayerNorm over last dim (768)
// ---------------------------------------------------------------------------
__global__ __launch_bounds__(256) void ln_kernel(
    const float* __restrict__ x, const float* __restrict__ gamma,
    const float* __restrict__ beta, float* __restrict__ out)
{
    const int row = blockIdx.x;
    const float* xr = x + (size_t)row * D_MODEL;
    const int tid = threadIdx.x;

    float v[3];
    float s = 0.f, s2 = 0.f;
#pragma unroll
    for (int i = 0; i < 3; i++) {
        v[i] = xr[tid + i * 256];
        s += v[i];
        s2 += v[i] * v[i];
    }
#pragma unroll
    for (int off = 16; off; off >>= 1) {
        s  += __shfl_xor_sync(0xffffffffu, s,  off);
        s2 += __shfl_xor_sync(0xffffffffu, s2, off);
    }
    __shared__ float rs[8], rs2[8];
    __shared__ float mu_s, rstd_s;
    const int w = tid >> 5;
    if ((tid & 31) == 0) { rs[w] = s; rs2[w] = s2; }
    __syncthreads();
    if (tid == 0) {
        float a = 0.f, bq = 0.f;
#pragma unroll
        for (int i = 0; i < 8; i++) { a += rs[i]; bq += rs2[i]; }
        float mu = a * (1.f / D_MODEL);
        float var = bq * (1.f / D_MODEL) - mu * mu;
        mu_s = mu;
        rstd_s = rsqrtf(var + 1e-5f);
    }
    __syncthreads();
    const float mu = mu_s, rstd = rstd_s;
#pragma unroll
    for (int i = 0; i < 3; i++) {
        int c = tid + i * 256;
        out[(size_t)row * D_MODEL + c] = (v[i] - mu) * rstd * gamma[c] + beta[c];
    }
}

// ---------------------------------------------------------------------------
// kernel_launch — inputs: Q, W_q, b_q, W_k, b_k, W_v, b_v, W_o, b_o,
//                         ln_gamma, ln_beta
// ---------------------------------------------------------------------------
extern "C" void kernel_launch(void* const* d_in, const int* in_sizes, int n_in,
                              void* d_out, int out_size)
{
    const float* Q     = (const float*)d_in[0];
    const float* Wq    = (const float*)d_in[1];
    const float* bq    = (const float*)d_in[2];
    const float* Wk    = (const float*)d_in[3];
    const float* bk    = (const float*)d_in[4];
    const float* Wv    = (const float*)d_in[5];
    const float* bv    = (const float*)d_in[6];
    const float* Wo    = (const float*)d_in[7];
    const float* bo    = (const float*)d_in[8];
    const float* gamma = (const float*)d_in[9];
    const float* beta  = (const float*)d_in[10];
    float* out = (float*)d_out;

    const int M = in_sizes[0] / D_MODEL;   // 4096
    const int B = M / SEQ;                 // 2

    float *q, *k, *v, *att, *x;
    cudaGetSymbolAddress((void**)&q,   g_q);
    cudaGetSymbolAddress((void**)&k,   g_k);
    cudaGetSymbolAddress((void**)&v,   g_v);
    cudaGetSymbolAddress((void**)&att, g_att);
    cudaGetSymbolAddress((void**)&x,   g_x);

    cudaFuncSetAttribute((const void*)attn_wm,
                         cudaFuncAttributeMaxDynamicSharedMemorySize, AT_SMEM);

    dim3 gg(D_MODEL / 128, M / 128);   // (6, 32)

    gemm_wm<<<gg, 256>>>(Q, Wq, bq, nullptr, q, M, D_MODEL, D_MODEL);
    gemm_wm<<<gg, 256>>>(Q, Wk, bk, nullptr, k, M, D_MODEL, D_MODEL);
    gemm_wm<<<gg, 256>>>(Q, Wv, bv, nullptr, v, M, D_MODEL, D_MODEL);

    attn_wm<<<dim3(SEQ / 128, NHEADS, B), 256, AT_SMEM>>>(q, k, v, att);

    gemm_wm<<<gg, 256>>>(att, Wo, bo, Q, x, M, D_MODEL, D_MODEL);

    ln_kernel<<<M, 256>>>(x, gamma, beta, out);
}

// round 4
// speedup vs baseline: 2.7098x; 1.4116x over previous
#include <cuda_runtime.h>
#include <cuda_bf16.h>
#include <cstdint>

// ---------------------------------------------------------------------------
// Problem constants
// ---------------------------------------------------------------------------
#define D_MODEL 768
#define SEQ     2048
#define NHEADS  12
#define DH      64
#define MROWS   (2 * SEQ)
#define WSZ     (D_MODEL * D_MODEL)

// ---------------------------------------------------------------------------
// Global scratch (allocation-free rule)
// ---------------------------------------------------------------------------
__device__ __nv_bfloat16 g_xh[MROWS * D_MODEL], g_xl[MROWS * D_MODEL];
__device__ __nv_bfloat16 g_wh[4 * WSZ],        g_wl[4 * WSZ];
// head-major [h][m][64] bf16
__device__ __nv_bfloat16 g_qh[NHEADS * MROWS * DH], g_ql[NHEADS * MROWS * DH];
__device__ __nv_bfloat16 g_kh[NHEADS * MROWS * DH], g_kl[NHEADS * MROWS * DH];
__device__ __nv_bfloat16 g_vh[NHEADS * MROWS * DH], g_vl[NHEADS * MROWS * DH];
__device__ __nv_bfloat16 g_ath[MROWS * D_MODEL], g_atl[MROWS * D_MODEL];
__device__ float g_x[MROWS * D_MODEL];

// ---------------------------------------------------------------------------
// PTX helpers (sm_80-level: mma.sync, ldmatrix, cp.async — safe for sm_100)
// ---------------------------------------------------------------------------
__device__ __forceinline__ uint32_t smem_u32(const void* p) {
    uint32_t a;
    asm("{ .reg .u64 t; cvta.to.shared.u64 t, %1; cvt.u32.u64 %0, t; }"
        : "=r"(a) : "l"(p));
    return a;
}

#define MMA_BF16(d, a, b) \
    asm volatile("mma.sync.aligned.m16n8k16.row.col.f32.bf16.bf16.f32 " \
        "{%0,%1,%2,%3}, {%4,%5,%6,%7}, {%8,%9}, {%0,%1,%2,%3};" \
        : "+f"((d)[0]), "+f"((d)[1]), "+f"((d)[2]), "+f"((d)[3]) \
        : "r"((a)[0]), "r"((a)[1]), "r"((a)[2]), "r"((a)[3]), \
          "r"((b)[0]), "r"((b)[1]))

#define LDSM4(r, addr) \
    asm volatile("ldmatrix.sync.aligned.m8n8.x4.shared.b16 {%0,%1,%2,%3}, [%4];" \
        : "=r"((r)[0]), "=r"((r)[1]), "=r"((r)[2]), "=r"((r)[3]) : "r"(addr))

#define LDSM4T(r, addr) \
    asm volatile("ldmatrix.sync.aligned.m8n8.x4.trans.shared.b16 {%0,%1,%2,%3}, [%4];" \
        : "=r"((r)[0]), "=r"((r)[1]), "=r"((r)[2]), "=r"((r)[3]) : "r"(addr))

#define CP16(dst, src) \
    asm volatile("cp.async.cg.shared.global [%0], [%1], 16;" \
                 :: "r"(dst), "l"(src))
#define CP_COMMIT() asm volatile("cp.async.commit_group;" ::: "memory")
#define CP_WAIT(N)  asm volatile("cp.async.wait_group %0;" :: "n"(N) : "memory")

// split (x,y) fp32 -> packed bf16 hi pair (lo16=x) and lo residual pair
__device__ __forceinline__ void cvt_hilo(float x, float y, uint32_t& h2, uint32_t& l2) {
    uint32_t h;
    asm("cvt.rn.bf16x2.f32 %0, %1, %2;" : "=r"(h) : "f"(y), "f"(x));
    float hx = __uint_as_float(h << 16);
    float hy = __uint_as_float(h & 0xffff0000u);
    uint32_t l;
    float lx = x - hx, ly = y - hy;
    asm("cvt.rn.bf16x2.f32 %0, %1, %2;" : "=r"(l) : "f"(ly), "f"(lx));
    h2 = h; l2 = l;
}

// ---------------------------------------------------------------------------
// Elementwise fp32 -> bf16 hi/lo split
// ---------------------------------------------------------------------------
__global__ void split_kernel(const float* __restrict__ src,
                             __nv_bfloat16* __restrict__ hi,
                             __nv_bfloat16* __restrict__ lo, int n4)
{
    uint32_t* h4 = (uint32_t*)hi;
    uint32_t* l4 = (uint32_t*)lo;
    for (int i = blockIdx.x * blockDim.x + threadIdx.x; i < n4;
         i += gridDim.x * blockDim.x) {
        float4 v = ((const float4*)src)[i];
        uint32_t h0, l0, h1, l1;
        cvt_hilo(v.x, v.y, h0, l0);
        cvt_hilo(v.z, v.w, h1, l1);
        h4[2 * i] = h0; h4[2 * i + 1] = h1;
        l4[2 * i] = l0; l4[2 * i + 1] = l1;
    }
}

// ---------------------------------------------------------------------------
// GEMM on pre-split hi/lo bf16:  C = A @ B.T (+bias)(+R), 3-MMA fp32 emu.
// CTA 128x128, BK=64, 2-stage cp.async pipeline, 8 warps (4m x 2n).
// MODE 0: fp32 C = acc + bias + R
// MODE 1: head-major bf16 hi/lo out, (acc + bias) * scale
// smem: 2 stages x 4 tiles(Ah,Al,Bh,Bl) x 128 rows x 144B = 147456 B
// ---------------------------------------------------------------------------
#define G_STG 73728
#define G_TIL 18432
#define G_SMEM (2 * G_STG)

template <int MODE>
__global__ __launch_bounds__(256) void gemm_bs(
    const __nv_bfloat16* __restrict__ Ah, const __nv_bfloat16* __restrict__ Al,
    const __nv_bfloat16* __restrict__ Bh, const __nv_bfloat16* __restrict__ Bl,
    const float* __restrict__ bias, const float* __restrict__ R,
    float* __restrict__ C,
    __nv_bfloat16* __restrict__ Oh, __nv_bfloat16* __restrict__ Ol,
    float scale)
{
    extern __shared__ char sm[];
    const uint32_t sb = smem_u32(sm);
    const int tid = threadIdx.x;
    const int lane = tid & 31;
    const int warp = tid >> 5;
    const int wm = warp >> 1;
    const int wn = warp & 1;
    const int bm = blockIdx.y * 128;
    const int bn = blockIdx.x * 128;

    const __nv_bfloat16* tsrc[4] = {Ah, Al, Bh, Bl};

    // stage loader: 4 tiles x 128 rows x 8 16B-chunks = 4096 chunks
    auto load_stage = [&](int kt, int st) {
        const uint32_t dst0 = sb + st * G_STG;
#pragma unroll
        for (int i = 0; i < 16; i++) {
            const int c = tid + i * 256;
            const int t = c >> 10;
            const int r = (c >> 3) & 127;
            const int ch = c & 7;
            const int grow = ((t < 2) ? bm : bn) + r;
            const char* src = (const char*)(tsrc[t] + (size_t)grow * D_MODEL + kt * 64)
                            + ch * 16;
            CP16(dst0 + t * G_TIL + r * 144 + ch * 16, src);
        }
        CP_COMMIT();
    };

    load_stage(0, 0);
    load_stage(1, 1);
    CP_WAIT(1);
    __syncthreads();

    float acc[2][8][4];
#pragma unroll
    for (int mt = 0; mt < 2; mt++)
#pragma unroll
        for (int nt = 0; nt < 8; nt++)
#pragma unroll
            for (int c = 0; c < 4; c++) acc[mt][nt][c] = 0.f;

    for (int kt = 0; kt < 12; kt++) {
        const uint32_t sA = sb + (kt & 1) * G_STG;
#pragma unroll
        for (int ks = 0; ks < 4; ks++) {
            uint32_t ah[2][4], al[2][4];
#pragma unroll
            for (int mt = 0; mt < 2; mt++) {
                const uint32_t off = (uint32_t)(wm * 32 + mt * 16 + (lane & 15)) * 144
                                   + (uint32_t)(ks * 16 + (lane >> 4) * 8) * 2;
                LDSM4(ah[mt], sA + off);
                LDSM4(al[mt], sA + G_TIL + off);
            }
            uint32_t bh[8][2], bl[8][2];
            {
                const int g = lane >> 3;
                const int nr = wn * 64 + (lane & 7) + ((g & 2) ? 8 : 0);
                const int kf = ks * 16 + (g & 1) * 8;
#pragma unroll
                for (int np = 0; np < 4; np++) {
                    const uint32_t off = (uint32_t)(nr + np * 16) * 144 + (uint32_t)kf * 2;
                    LDSM4(&bh[np * 2][0], sA + 2 * G_TIL + off);
                    LDSM4(&bl[np * 2][0], sA + 3 * G_TIL + off);
                }
            }
#pragma unroll
            for (int mt = 0; mt < 2; mt++)
#pragma unroll
                for (int nt = 0; nt < 8; nt++) {
                    MMA_BF16(acc[mt][nt], ah[mt], bh[nt]);
                    MMA_BF16(acc[mt][nt], ah[mt], bl[nt]);
                    MMA_BF16(acc[mt][nt], al[mt], bh[nt]);
                }
        }
        __syncthreads();
        if (kt < 10) {
            load_stage(kt + 2, kt & 1);
            CP_WAIT(1);
        } else {
            CP_WAIT(0);
        }
        __syncthreads();
    }

    // epilogue
#pragma unroll
    for (int mt = 0; mt < 2; mt++)
#pragma unroll
        for (int hh = 0; hh < 2; hh++) {
            const int m = bm + wm * 32 + mt * 16 + (lane >> 2) + hh * 8;
#pragma unroll
            for (int nt = 0; nt < 8; nt++) {
                const int col = bn + wn * 64 + nt * 8 + (lane & 3) * 2;
                float x0 = acc[mt][nt][2 * hh]     + bias[col];
                float x1 = acc[mt][nt][2 * hh + 1] + bias[col + 1];
                if (MODE == 0) {
                    const float2 rr = *(const float2*)(R + (size_t)m * D_MODEL + col);
                    float2 v = {x0 + rr.x, x1 + rr.y};
                    *(float2*)(C + (size_t)m * D_MODEL + col) = v;
                } else {
                    x0 *= scale; x1 *= scale;
                    uint32_t hp, lp;
                    cvt_hilo(x0, x1, hp, lp);
                    const int hd = col >> 6;
                    const int dh = col & 63;
                    const size_t oi = ((size_t)hd * MROWS + m) * 32 + (dh >> 1);
                    ((uint32_t*)Oh)[oi] = hp;
                    ((uint32_t*)Ol)[oi] = lp;
                }
            }
        }
}

// ---------------------------------------------------------------------------
// Flash attention on pre-split head-major bf16 hi/lo q/k/v.
// CTA = (128 q rows, head, batch); 8 warps, each owns 16 q rows (private
// softmax). KV tiles of 64 keys, 2-stage cp.async pipeline, 32 iters.
// Emits att as row-major bf16 hi/lo.
// smem: Qhi/Qlo 128x144 x2 = 36864; KV stages 2 x 4 x 64x144 = 73728.
// ---------------------------------------------------------------------------
#define AQ_TIL 18432
#define AKV0   36864
#define AKV_T  9216
#define AKV_S  36864
#define A_SMEM (AKV0 + 2 * AKV_S)   // 110592

__global__ __launch_bounds__(256) void attn_bs(
    const __nv_bfloat16* __restrict__ qh_g, const __nv_bfloat16* __restrict__ ql_g,
    const __nv_bfloat16* __restrict__ kh_g, const __nv_bfloat16* __restrict__ kl_g,
    const __nv_bfloat16* __restrict__ vh_g, const __nv_bfloat16* __restrict__ vl_g,
    __nv_bfloat16* __restrict__ ath, __nv_bfloat16* __restrict__ atl)
{
    extern __shared__ char sm[];
    const uint32_t sb = smem_u32(sm);
    const int tid = threadIdx.x;
    const int lane = tid & 31;
    const int w = tid >> 5;
    const int qb = blockIdx.x * 128;
    const int h = blockIdx.y;
    const int b = blockIdx.z;
    const size_t hq = (size_t)h * MROWS + (size_t)b * SEQ;   // head-major row base

    const __nv_bfloat16* kvsrc[4] = {kh_g, kl_g, vh_g, vl_g};

    // Q loader: 2 tiles x 128 rows x 8 chunks = 2048
    {
#pragma unroll
        for (int i = 0; i < 8; i++) {
            const int c = tid + i * 256;
            const int t = c >> 10;
            const int r = (c >> 3) & 127;
            const int ch = c & 7;
            const char* src = (const char*)((t ? ql_g : qh_g) + (hq + qb + r) * DH)
                            + ch * 16;
            CP16(sb + t * AQ_TIL + r * 144 + ch * 16, src);
        }
        CP_COMMIT();
    }

    auto load_kv = [&](int it, int st) {
        const int kv = it * 64;
        const uint32_t dst0 = sb + AKV0 + st * AKV_S;
#pragma unroll
        for (int i = 0; i < 8; i++) {
            const int c = tid + i * 256;
            const int t = c >> 9;
            const int r = (c >> 3) & 63;
            const int ch = c & 7;
            const char* src = (const char*)(kvsrc[t] + (hq + kv + r) * DH) + ch * 16;
            CP16(dst0 + t * AKV_T + r * 144 + ch * 16, src);
        }
        CP_COMMIT();
    };

    load_kv(0, 0);
    load_kv(1, 1);
    CP_WAIT(1);          // Q + stage0 complete
    __syncthreads();

    // hoist Q fragments into registers (reused for all 32 iterations)
    uint32_t qfh[4][4], qfl[4][4];
#pragma unroll
    for (int ks = 0; ks < 4; ks++) {
        const uint32_t off = (uint32_t)(w * 16 + (lane & 15)) * 144
                           + (uint32_t)(ks * 16 + (lane >> 4) * 8) * 2;
        LDSM4(qfh[ks], sb + off);
        LDSM4(qfl[ks], sb + AQ_TIL + off);
    }

    float o[8][4];
    float m_run[2] = {-1e30f, -1e30f}, l_run[2] = {0.f, 0.f};
#pragma unroll
    for (int nt = 0; nt < 8; nt++)
#pragma unroll
        for (int c = 0; c < 4; c++) o[nt][c] = 0.f;

    for (int it = 0; it < 32; it++) {
        const uint32_t sKh = sb + AKV0 + (it & 1) * AKV_S;
        const uint32_t sKl = sKh + AKV_T;
        const uint32_t sVh = sKh + 2 * AKV_T;
        const uint32_t sVl = sKh + 3 * AKV_T;

        // ---- S = Q K^T  (16 q x 64 keys) ----
        float s[8][4];
#pragma unroll
        for (int nt = 0; nt < 8; nt++)
#pragma unroll
            for (int c = 0; c < 4; c++) s[nt][c] = 0.f;

#pragma unroll
        for (int ks = 0; ks < 4; ks++) {
            uint32_t kh_[8][2], kl_[8][2];
            const int g = lane >> 3;
            const int nr = (lane & 7) + ((g & 2) ? 8 : 0);
            const int kf = ks * 16 + (g & 1) * 8;
#pragma unroll
            for (int np = 0; np < 4; np++) {
                const uint32_t off = (uint32_t)(nr + np * 16) * 144 + (uint32_t)kf * 2;
                LDSM4(&kh_[np * 2][0], sKh + off);
                LDSM4(&kl_[np * 2][0], sKl + off);
            }
#pragma unroll
            for (int nt = 0; nt < 8; nt++) {
                MMA_BF16(s[nt], qfh[ks], kh_[nt]);
                MMA_BF16(s[nt], qfh[ks], kl_[nt]);
                MMA_BF16(s[nt], qfl[ks], kh_[nt]);
            }
        }

        // ---- warp-private online softmax (2 rows per thread) ----
        float corr[2];
#pragma unroll
        for (int hh = 0; hh < 2; hh++) {
            float m = -1e30f;
#pragma unroll
            for (int nt = 0; nt < 8; nt++)
                m = fmaxf(m, fmaxf(s[nt][2 * hh], s[nt][2 * hh + 1]));
            m = fmaxf(m, __shfl_xor_sync(0xffffffffu, m, 1));
            m = fmaxf(m, __shfl_xor_sync(0xffffffffu, m, 2));
            const float mn = fmaxf(m_run[hh], m);
            corr[hh] = __expf(m_run[hh] - mn);
            m_run[hh] = mn;
        }
        float ps[2] = {0.f, 0.f};
#pragma unroll
        for (int nt = 0; nt < 8; nt++)
#pragma unroll
            for (int c = 0; c < 4; c++) {
                const float p = __expf(s[nt][c] - m_run[c >> 1]);
                s[nt][c] = p;
                ps[c >> 1] += p;
            }
#pragma unroll
        for (int hh = 0; hh < 2; hh++) {
            float v = ps[hh];
            v += __shfl_xor_sync(0xffffffffu, v, 1);
            v += __shfl_xor_sync(0xffffffffu, v, 2);
            l_run[hh] = l_run[hh] * corr[hh] + v;
        }
#pragma unroll
        for (int nt = 0; nt < 8; nt++)
#pragma unroll
            for (int c = 0; c < 4; c++) o[nt][c] *= corr[c >> 1];

        // ---- O += P V (register P hi/lo, ldmatrix.trans V) ----
#pragma unroll
        for (int kc = 0; kc < 4; kc++) {
            uint32_t ph[4], pl[4];
            cvt_hilo(s[2 * kc][0],     s[2 * kc][1],     ph[0], pl[0]);
            cvt_hilo(s[2 * kc][2],     s[2 * kc][3],     ph[1], pl[1]);
            cvt_hilo(s[2 * kc + 1][0], s[2 * kc + 1][1], ph[2], pl[2]);
            cvt_hilo(s[2 * kc + 1][2], s[2 * kc + 1][3], ph[3], pl[3]);
            uint32_t vh_[8][2], vl_[8][2];
            const int g = lane >> 3;
            const int kr = kc * 16 + (lane & 7) + ((g & 1) ? 8 : 0);
            const int nf = (g & 2) ? 8 : 0;
#pragma unroll
            for (int np = 0; np < 4; np++) {
                const uint32_t off = (uint32_t)kr * 144 + (uint32_t)(np * 16 + nf) * 2;
                LDSM4T(&vh_[np * 2][0], sVh + off);
                LDSM4T(&vl_[np * 2][0], sVl + off);
            }
#pragma unroll
            for (int nt = 0; nt < 8; nt++) {
                MMA_BF16(o[nt], ph, vh_[nt]);
                MMA_BF16(o[nt], ph, vl_[nt]);
                MMA_BF16(o[nt], pl, vh_[nt]);
            }
        }

        __syncthreads();
        if (it < 30) {
            load_kv(it + 2, it & 1);
            CP_WAIT(1);
        } else {
            CP_WAIT(0);
        }
        __syncthreads();
    }

    // ---- epilogue: att as bf16 hi/lo, row-major [M][768] ----
#pragma unroll
    for (int hh = 0; hh < 2; hh++) {
        const float inv = 1.f / l_run[hh];
        const size_t m = (size_t)b * SEQ + qb + w * 16 + (lane >> 2) + hh * 8;
#pragma unroll
        for (int nt = 0; nt < 8; nt++) {
            const int col = h * 64 + nt * 8 + (lane & 3) * 2;
            uint32_t hp, lp;
            cvt_hilo(o[nt][2 * hh] * inv, o[nt][2 * hh + 1] * inv, hp, lp);
            const size_t oi = (m * D_MODEL + col) >> 1;
            ((uint32_t*)ath)[oi] = hp;
            ((uint32_t*)atl)[oi] = lp;
        }
    }
}

// ---------------------------------------------------------------------------
// LayerNorm over last dim (768)
// ---------------------------------------------------------------------------
__global__ __launch_bounds__(256) void ln_kernel(
    const float* __restrict__ x, const float* __restrict__ gamma,
    const float* __restrict__ beta, float* __restrict__ out)
{
    const int row = blockIdx.x;
    const float* xr = x + (size_t)row * D_MODEL;
    const int tid = threadIdx.x;

    float v[3];
    float s = 0.f, s2 = 0.f;
#pragma unroll
    for (int i = 0; i < 3; i++) {
        v[i] = xr[tid + i * 256];
        s += v[i];
        s2 += v[i] * v[i];
    }
#pragma unroll
    for (int off = 16; off; off >>= 1) {
        s  += __shfl_xor_sync(0xffffffffu, s,  off);
        s2 += __shfl_xor_sync(0xffffffffu, s2, off);
    }
    __shared__ float rs[8], rs2[8];
    __shared__ float mu_s, rstd_s;
    const int w = tid >> 5;
    if ((tid & 31) == 0) { rs[w] = s; rs2[w] = s2; }
    __syncthreads();
    if (tid == 0) {
        float a = 0.f, bq = 0.f;
#pragma unroll
        for (int i = 0; i < 8; i++) { a += rs[i]; bq += rs2[i]; }
        float mu = a * (1.f / D_MODEL);
        float var = bq * (1.f / D_MODEL) - mu * mu;
        mu_s = mu;
        rstd_s = rsqrtf(var + 1e-5f);
    }
    __syncthreads();
    const float mu = mu_s, rstd = rstd_s;
#pragma unroll
    for (int i = 0; i < 3; i++) {
        int c = tid + i * 256;
        out[(size_t)row * D_MODEL + c] = (v[i] - mu) * rstd * gamma[c] + beta[c];
    }
}

// ---------------------------------------------------------------------------
// kernel_launch — inputs: Q, W_q, b_q, W_k, b_k, W_v, b_v, W_o, b_o,
//                         ln_gamma, ln_beta
// ---------------------------------------------------------------------------
extern "C" void kernel_launch(void* const* d_in, const int* in_sizes, int n_in,
                              void* d_out, int out_size)
{
    const float* X     = (const float*)d_in[0];
    const float* Wq    = (const float*)d_in[1];
    const float* bq    = (const float*)d_in[2];
    const float* Wk    = (const float*)d_in[3];
    const float* bk    = (const float*)d_in[4];
    const float* Wv    = (const float*)d_in[5];
    const float* bv    = (const float*)d_in[6];
    const float* Wo    = (const float*)d_in[7];
    const float* bo    = (const float*)d_in[8];
    const float* gamma = (const float*)d_in[9];
    const float* beta  = (const float*)d_in[10];
    float* out = (float*)d_out;

    const int M = in_sizes[0] / D_MODEL;   // 4096
    const int B = M / SEQ;                 // 2

    __nv_bfloat16 *xh, *xl, *wh, *wl, *qh, *ql, *kh, *kl, *vh, *vl, *ath, *atl;
    float* x;
    cudaGetSymbolAddress((void**)&xh, g_xh);  cudaGetSymbolAddress((void**)&xl, g_xl);
    cudaGetSymbolAddress((void**)&wh, g_wh);  cudaGetSymbolAddress((void**)&wl, g_wl);
    cudaGetSymbolAddress((void**)&qh, g_qh);  cudaGetSymbolAddress((void**)&ql, g_ql);
    cudaGetSymbolAddress((void**)&kh, g_kh);  cudaGetSymbolAddress((void**)&kl, g_kl);
    cudaGetSymbolAddress((void**)&vh, g_vh);  cudaGetSymbolAddress((void**)&vl, g_vl);
    cudaGetSymbolAddress((void**)&ath, g_ath); cudaGetSymbolAddress((void**)&atl, g_atl);
    cudaGetSymbolAddress((void**)&x, g_x);

    cudaFuncSetAttribute((const void*)gemm_bs<0>,
                         cudaFuncAttributeMaxDynamicSharedMemorySize, G_SMEM);
    cudaFuncSetAttribute((const void*)gemm_bs<1>,
                         cudaFuncAttributeMaxDynamicSharedMemorySize, G_SMEM);
    cudaFuncSetAttribute((const void*)attn_bs,
                         cudaFuncAttributeMaxDynamicSharedMemorySize, A_SMEM);

    // 1) pre-split input + weights
    split_kernel<<<768, 256>>>(X, xh, xl, M * D_MODEL / 4);
    split_kernel<<<576, 256>>>(Wq, wh + 0 * WSZ, wl + 0 * WSZ, WSZ / 4);
    split_kernel<<<576, 256>>>(Wk, wh + 1 * WSZ, wl + 1 * WSZ, WSZ / 4);
    split_kernel<<<576, 256>>>(Wv, wh + 2 * WSZ, wl + 2 * WSZ, WSZ / 4);
    split_kernel<<<576, 256>>>(Wo, wh + 3 * WSZ, wl + 3 * WSZ, WSZ / 4);

    dim3 gg(D_MODEL / 128, M / 128);   // (6, 32)

    // 2) QKV projections -> head-major bf16 hi/lo (Q scaled by 1/8)
    gemm_bs<1><<<gg, 256, G_SMEM>>>(xh, xl, wh + 0 * WSZ, wl + 0 * WSZ,
                                    bq, nullptr, nullptr, qh, ql, 0.125f);
    gemm_bs<1><<<gg, 256, G_SMEM>>>(xh, xl, wh + 1 * WSZ, wl + 1 * WSZ,
                                    bk, nullptr, nullptr, kh, kl, 1.0f);
    gemm_bs<1><<<gg, 256, G_SMEM>>>(xh, xl, wh + 2 * WSZ, wl + 2 * WSZ,
                                    bv, nullptr, nullptr, vh, vl, 1.0f);

    // 3) attention -> att bf16 hi/lo
    attn_bs<<<dim3(SEQ / 128, NHEADS, B), 256, A_SMEM>>>(qh, ql, kh, kl, vh, vl,
                                                         ath, atl);

    // 4) O-projection + residual -> fp32 x
    gemm_bs<0><<<gg, 256, G_SMEM>>>(ath, atl, wh + 3 * WSZ, wl + 3 * WSZ,
                                    bo, X, x, nullptr, nullptr, 1.0f);

    // 5) LayerNorm
    ln_kernel<<<M, 256>>>(x, gamma, beta, out);
}

// round 5
// speedup vs baseline: 3.0818x; 1.1373x over previous
#include <cuda_runtime.h>
#include <cuda_bf16.h>
#include <cstdint>

// ---------------------------------------------------------------------------
// Problem constants
// ---------------------------------------------------------------------------
#define D_MODEL 768
#define SEQ     2048
#define NHEADS  12
#define DH      64
#define MROWS   (2 * SEQ)
#define WSZ     (D_MODEL * D_MODEL)

// ---------------------------------------------------------------------------
// Global scratch (allocation-free rule)
// ---------------------------------------------------------------------------
__device__ __nv_bfloat16 g_xh[MROWS * D_MODEL], g_xl[MROWS * D_MODEL];
__device__ __nv_bfloat16 g_wh[4 * WSZ],        g_wl[4 * WSZ];
// head-major [h][m][64] bf16
__device__ __nv_bfloat16 g_qh[NHEADS * MROWS * DH], g_ql[NHEADS * MROWS * DH];
__device__ __nv_bfloat16 g_kh[NHEADS * MROWS * DH], g_kl[NHEADS * MROWS * DH];
__device__ __nv_bfloat16 g_vh[NHEADS * MROWS * DH], g_vl[NHEADS * MROWS * DH];
__device__ __nv_bfloat16 g_ath[MROWS * D_MODEL], g_atl[MROWS * D_MODEL];
__device__ float g_x[MROWS * D_MODEL];

// ---------------------------------------------------------------------------
// PTX helpers
// ---------------------------------------------------------------------------
__device__ __forceinline__ uint32_t smem_u32(const void* p) {
    uint32_t a;
    asm("{ .reg .u64 t; cvta.to.shared.u64 t, %1; cvt.u32.u64 %0, t; }"
        : "=r"(a) : "l"(p));
    return a;
}

#define MMA_BF16(d, a, b) \
    asm volatile("mma.sync.aligned.m16n8k16.row.col.f32.bf16.bf16.f32 " \
        "{%0,%1,%2,%3}, {%4,%5,%6,%7}, {%8,%9}, {%0,%1,%2,%3};" \
        : "+f"((d)[0]), "+f"((d)[1]), "+f"((d)[2]), "+f"((d)[3]) \
        : "r"((a)[0]), "r"((a)[1]), "r"((a)[2]), "r"((a)[3]), \
          "r"((b)[0]), "r"((b)[1]))

#define LDSM4(r, addr) \
    asm volatile("ldmatrix.sync.aligned.m8n8.x4.shared.b16 {%0,%1,%2,%3}, [%4];" \
        : "=r"((r)[0]), "=r"((r)[1]), "=r"((r)[2]), "=r"((r)[3]) : "r"(addr))

#define LDSM4T(r, addr) \
    asm volatile("ldmatrix.sync.aligned.m8n8.x4.trans.shared.b16 {%0,%1,%2,%3}, [%4];" \
        : "=r"((r)[0]), "=r"((r)[1]), "=r"((r)[2]), "=r"((r)[3]) : "r"(addr))

#define CP16(dst, src) \
    asm volatile("cp.async.cg.shared.global [%0], [%1], 16;" \
                 :: "r"(dst), "l"(src))
#define CP_COMMIT() asm volatile("cp.async.commit_group;" ::: "memory")
#define CP_WAIT(N)  asm volatile("cp.async.wait_group %0;" :: "n"(N) : "memory")

// split (x,y) fp32 -> packed bf16 hi pair (lo16=x) and lo residual pair
__device__ __forceinline__ void cvt_hilo(float x, float y, uint32_t& h2, uint32_t& l2) {
    uint32_t h;
    asm("cvt.rn.bf16x2.f32 %0, %1, %2;" : "=r"(h) : "f"(y), "f"(x));
    float hx = __uint_as_float(h << 16);
    float hy = __uint_as_float(h & 0xffff0000u);
    uint32_t l;
    float lx = x - hx, ly = y - hy;
    asm("cvt.rn.bf16x2.f32 %0, %1, %2;" : "=r"(l) : "f"(ly), "f"(lx));
    h2 = h; l2 = l;
}

// ---------------------------------------------------------------------------
// One merged split pass: X and the four weights -> bf16 hi/lo
// ---------------------------------------------------------------------------
struct SplitSrcs { const float* p[5]; };

#define NX4 (MROWS * D_MODEL / 4)   // 786432
#define NW4 (WSZ / 4)               // 147456

__global__ void split_all(SplitSrcs s,
                          __nv_bfloat16* __restrict__ xh, __nv_bfloat16* __restrict__ xl,
                          __nv_bfloat16* __restrict__ wh, __nv_bfloat16* __restrict__ wl)
{
    const int total = NX4 + 4 * NW4;
    for (int i = blockIdx.x * blockDim.x + threadIdx.x; i < total;
         i += gridDim.x * blockDim.x) {
        int seg, off;
        if (i < NX4) { seg = 0; off = i; }
        else { const int j = i - NX4; seg = 1 + j / NW4; off = j - (seg - 1) * NW4; }
        const float4 v = ((const float4*)s.p[seg])[off];
        uint32_t h0, l0, h1, l1;
        cvt_hilo(v.x, v.y, h0, l0);
        cvt_hilo(v.z, v.w, h1, l1);
        uint32_t* dh;
        uint32_t* dl;
        if (seg == 0) { dh = (uint32_t*)xh; dl = (uint32_t*)xl; }
        else {
            dh = (uint32_t*)(wh + (size_t)(seg - 1) * WSZ);
            dl = (uint32_t*)(wl + (size_t)(seg - 1) * WSZ);
        }
        dh[2 * off] = h0; dh[2 * off + 1] = h1;
        dl[2 * off] = l0; dl[2 * off + 1] = l1;
    }
}

// ---------------------------------------------------------------------------
// GEMM on pre-split hi/lo bf16 (3-MMA fp32 emulation).
// CTA 128x128, BK=32, 2-stage cp.async, 8 warps (4m x 2n), 2 CTAs/SM.
// MODE 0: O-proj  -> fp32 C = acc + bias + R       (grid z = 1)
// MODE 1: QKV     -> head-major bf16 hi/lo, z=blockIdx.z picks W/bias/out
// smem: 2 stages x 4 tiles x 128 rows x 80B = 81920 B
// ---------------------------------------------------------------------------
#define G_TIL 10240
#define G_STG 40960
#define G_SMEM (2 * G_STG)

struct GemmAux {
    const float* bias[3];
    __nv_bfloat16* oh[3];
    __nv_bfloat16* ol[3];
    const float* R;
    float* C;
};

template <int MODE>
__global__ __launch_bounds__(256, 2) void gemm_bs(
    const __nv_bfloat16* __restrict__ Ah, const __nv_bfloat16* __restrict__ Al,
    const __nv_bfloat16* __restrict__ WhB, const __nv_bfloat16* __restrict__ WlB,
    GemmAux aux)
{
    extern __shared__ char sm[];
    const uint32_t sb = smem_u32(sm);
    const int tid = threadIdx.x;
    const int lane = tid & 31;
    const int warp = tid >> 5;
    const int wm = warp >> 1;
    const int wn = warp & 1;
    const int bm = blockIdx.y * 128;
    const int bn = blockIdx.x * 128;
    const int z = (MODE == 1) ? blockIdx.z : 0;

    const __nv_bfloat16* Bh = WhB + (size_t)z * WSZ;
    const __nv_bfloat16* Bl = WlB + (size_t)z * WSZ;
    const float* bias = aux.bias[z];

    const __nv_bfloat16* tsrc[4] = {Ah, Al, Bh, Bl};

    // stage loader: 4 tiles x 128 rows x 4 chunks = 2048; 8 per thread
    auto load_stage = [&](int kt, int st) {
        const uint32_t dst0 = sb + st * G_STG;
#pragma unroll
        for (int i = 0; i < 8; i++) {
            const int c = tid + i * 256;
            const int t = c >> 9;
            const int r = (c >> 2) & 127;
            const int ch = c & 3;
            const int grow = ((t < 2) ? bm : bn) + r;
            const char* src = (const char*)(tsrc[t] + (size_t)grow * D_MODEL + kt * 32)
                            + ch * 16;
            CP16(dst0 + t * G_TIL + r * 80 + ch * 16, src);
        }
        CP_COMMIT();
    };

    load_stage(0, 0);
    load_stage(1, 1);
    CP_WAIT(1);
    __syncthreads();

    float acc[2][8][4];
#pragma unroll
    for (int mt = 0; mt < 2; mt++)
#pragma unroll
        for (int nt = 0; nt < 8; nt++)
#pragma unroll
            for (int c = 0; c < 4; c++) acc[mt][nt][c] = 0.f;

    for (int kt = 0; kt < 24; kt++) {
        const uint32_t sA = sb + (kt & 1) * G_STG;
#pragma unroll
        for (int ks = 0; ks < 2; ks++) {
            uint32_t ah[2][4], al[2][4];
#pragma unroll
            for (int mt = 0; mt < 2; mt++) {
                const uint32_t off = (uint32_t)(wm * 32 + mt * 16 + (lane & 15)) * 80
                                   + (uint32_t)(ks * 16 + (lane >> 4) * 8) * 2;
                LDSM4(ah[mt], sA + off);
                LDSM4(al[mt], sA + G_TIL + off);
            }
#pragma unroll
            for (int half = 0; half < 2; half++) {
                uint32_t bh[4][2], bl[4][2];
                const int g = lane >> 3;
                const int nr = wn * 64 + half * 32 + (lane & 7) + ((g & 2) ? 8 : 0);
                const int kf = ks * 16 + (g & 1) * 8;
#pragma unroll
                for (int np = 0; np < 2; np++) {
                    const uint32_t off = (uint32_t)(nr + np * 16) * 80 + (uint32_t)kf * 2;
                    LDSM4(&bh[np * 2][0], sA + 2 * G_TIL + off);
                    LDSM4(&bl[np * 2][0], sA + 3 * G_TIL + off);
                }
#pragma unroll
                for (int mt = 0; mt < 2; mt++)
#pragma unroll
                    for (int n4 = 0; n4 < 4; n4++) {
                        const int nt = half * 4 + n4;
                        MMA_BF16(acc[mt][nt], ah[mt], bh[n4]);
                        MMA_BF16(acc[mt][nt], ah[mt], bl[n4]);
                        MMA_BF16(acc[mt][nt], al[mt], bh[n4]);
                    }
            }
        }
        __syncthreads();
        if (kt < 22) {
            load_stage(kt + 2, kt & 1);
            CP_WAIT(1);
        } else {
            CP_WAIT(0);
        }
        __syncthreads();
    }

    // epilogue
    const float scale = (MODE == 1 && z == 0) ? 0.125f : 1.0f;
#pragma unroll
    for (int mt = 0; mt < 2; mt++)
#pragma unroll
        for (int hh = 0; hh < 2; hh++) {
            const int m = bm + wm * 32 + mt * 16 + (lane >> 2) + hh * 8;
#pragma unroll
            for (int nt = 0; nt < 8; nt++) {
                const int col = bn + wn * 64 + nt * 8 + (lane & 3) * 2;
                float x0 = acc[mt][nt][2 * hh]     + bias[col];
                float x1 = acc[mt][nt][2 * hh + 1] + bias[col + 1];
                if (MODE == 0) {
                    const float2 rr = *(const float2*)(aux.R + (size_t)m * D_MODEL + col);
                    float2 v = {x0 + rr.x, x1 + rr.y};
                    *(float2*)(aux.C + (size_t)m * D_MODEL + col) = v;
                } else {
                    x0 *= scale; x1 *= scale;
                    uint32_t hp, lp;
                    cvt_hilo(x0, x1, hp, lp);
                    const int hd = col >> 6;
                    const int dh = col & 63;
                    const size_t oi = ((size_t)hd * MROWS + m) * 32 + (dh >> 1);
                    ((uint32_t*)aux.oh[z])[oi] = hp;
                    ((uint32_t*)aux.ol[z])[oi] = lp;
                }
            }
        }
}

// ---------------------------------------------------------------------------
// Flash attention on pre-split head-major bf16 hi/lo q/k/v.
// CTA = 128 threads (4 warps), 64 q rows; warp owns 16 q rows (private
// softmax). KV tiles of 64 keys, 2-stage cp.async, 32 iters. 2 CTAs/SM.
// smem: Q 2x9216 + KV stages 2x36864 = 92160 B
// ---------------------------------------------------------------------------
#define AQ_TIL 9216
#define AKV0   18432
#define AKV_T  9216
#define AKV_S  36864
#define A_SMEM (AKV0 + 2 * AKV_S)   // 92160

__global__ __launch_bounds__(128) void attn_bs(
    const __nv_bfloat16* __restrict__ qh_g, const __nv_bfloat16* __restrict__ ql_g,
    const __nv_bfloat16* __restrict__ kh_g, const __nv_bfloat16* __restrict__ kl_g,
    const __nv_bfloat16* __restrict__ vh_g, const __nv_bfloat16* __restrict__ vl_g,
    __nv_bfloat16* __restrict__ ath, __nv_bfloat16* __restrict__ atl)
{
    extern __shared__ char sm[];
    const uint32_t sb = smem_u32(sm);
    const int tid = threadIdx.x;
    const int lane = tid & 31;
    const int w = tid >> 5;
    const int qb = blockIdx.x * 64;
    const int h = blockIdx.y;
    const int b = blockIdx.z;
    const size_t hq = (size_t)h * MROWS + (size_t)b * SEQ;   // head-major row base

    const __nv_bfloat16* kvsrc[4] = {kh_g, kl_g, vh_g, vl_g};

    // Q loader: 2 tiles x 64 rows x 8 chunks = 1024; 8 per thread
    {
#pragma unroll
        for (int i = 0; i < 8; i++) {
            const int c = tid + i * 128;
            const int t = c >> 9;
            const int r = (c >> 3) & 63;
            const int ch = c & 7;
            const char* src = (const char*)((t ? ql_g : qh_g) + (hq + qb + r) * DH)
                            + ch * 16;
            CP16(sb + t * AQ_TIL + r * 144 + ch * 16, src);
        }
        CP_COMMIT();
    }

    auto load_kv = [&](int it, int st) {
        const int kv = it * 64;
        const uint32_t dst0 = sb + AKV0 + st * AKV_S;
#pragma unroll
        for (int i = 0; i < 16; i++) {
            const int c = tid + i * 128;
            const int t = c >> 9;
            const int r = (c >> 3) & 63;
            const int ch = c & 7;
            const char* src = (const char*)(kvsrc[t] + (hq + kv + r) * DH) + ch * 16;
            CP16(dst0 + t * AKV_T + r * 144 + ch * 16, src);
        }
        CP_COMMIT();
    };

    load_kv(0, 0);
    load_kv(1, 1);
    CP_WAIT(1);          // Q + stage0 complete
    __syncthreads();

    // hoist Q fragments into registers (reused for all 32 iterations)
    uint32_t qfh[4][4], qfl[4][4];
#pragma unroll
    for (int ks = 0; ks < 4; ks++) {
        const uint32_t off = (uint32_t)(w * 16 + (lane & 15)) * 144
                           + (uint32_t)(ks * 16 + (lane >> 4) * 8) * 2;
        LDSM4(qfh[ks], sb + off);
        LDSM4(qfl[ks], sb + AQ_TIL + off);
    }

    float o[8][4];
    float m_run[2] = {-1e30f, -1e30f}, l_run[2] = {0.f, 0.f};
#pragma unroll
    for (int nt = 0; nt < 8; nt++)
#pragma unroll
        for (int c = 0; c < 4; c++) o[nt][c] = 0.f;

    for (int it = 0; it < 32; it++) {
        const uint32_t sKh = sb + AKV0 + (it & 1) * AKV_S;
        const uint32_t sKl = sKh + AKV_T;
        const uint32_t sVh = sKh + 2 * AKV_T;
        const uint32_t sVl = sKh + 3 * AKV_T;

        // ---- S = Q K^T  (16 q x 64 keys) ----
        float s[8][4];
#pragma unroll
        for (int nt = 0; nt < 8; nt++)
#pragma unroll
            for (int c = 0; c < 4; c++) s[nt][c] = 0.f;

#pragma unroll
        for (int ks = 0; ks < 4; ks++) {
            uint32_t kh_[8][2], kl_[8][2];
            const int g = lane >> 3;
            const int nr = (lane & 7) + ((g & 2) ? 8 : 0);
            const int kf = ks * 16 + (g & 1) * 8;
#pragma unroll
            for (int np = 0; np < 4; np++) {
                const uint32_t off = (uint32_t)(nr + np * 16) * 144 + (uint32_t)kf * 2;
                LDSM4(&kh_[np * 2][0], sKh + off);
                LDSM4(&kl_[np * 2][0], sKl + off);
            }
#pragma unroll
            for (int nt = 0; nt < 8; nt++) {
                MMA_BF16(s[nt], qfh[ks], kh_[nt]);
                MMA_BF16(s[nt], qfh[ks], kl_[nt]);
                MMA_BF16(s[nt], qfl[ks], kh_[nt]);
            }
        }

        // ---- warp-private online softmax (2 rows per thread) ----
        float corr[2];
#pragma unroll
        for (int hh = 0; hh < 2; hh++) {
            float m = -1e30f;
#pragma unroll
            for (int nt = 0; nt < 8; nt++)
                m = fmaxf(m, fmaxf(s[nt][2 * hh], s[nt][2 * hh + 1]));
            m = fmaxf(m, __shfl_xor_sync(0xffffffffu, m, 1));
            m = fmaxf(m, __shfl_xor_sync(0xffffffffu, m, 2));
            const float mn = fmaxf(m_run[hh], m);
            corr[hh] = __expf(m_run[hh] - mn);
            m_run[hh] = mn;
        }
        float ps[2] = {0.f, 0.f};
#pragma unroll
        for (int nt = 0; nt < 8; nt++)
#pragma unroll
            for (int c = 0; c < 4; c++) {
                const float p = __expf(s[nt][c] - m_run[c >> 1]);
                s[nt][c] = p;
                ps[c >> 1] += p;
            }
#pragma unroll
        for (int hh = 0; hh < 2; hh++) {
            float v = ps[hh];
            v += __shfl_xor_sync(0xffffffffu, v, 1);
            v += __shfl_xor_sync(0xffffffffu, v, 2);
            l_run[hh] = l_run[hh] * corr[hh] + v;
        }
#pragma unroll
        for (int nt = 0; nt < 8; nt++)
#pragma unroll
            for (int c = 0; c < 4; c++) o[nt][c] *= corr[c >> 1];

        // ---- O += P V (register P hi/lo, ldmatrix.trans V) ----
#pragma unroll
        for (int kc = 0; kc < 4; kc++) {
            uint32_t ph[4], pl[4];
            cvt_hilo(s[2 * kc][0],     s[2 * kc][1],     ph[0], pl[0]);
            cvt_hilo(s[2 * kc][2],     s[2 * kc][3],     ph[1], pl[1]);
            cvt_hilo(s[2 * kc + 1][0], s[2 * kc + 1][1], ph[2], pl[2]);
            cvt_hilo(s[2 * kc + 1][2], s[2 * kc + 1][3], ph[3], pl[3]);
            uint32_t vh_[8][2], vl_[8][2];
            const int g = lane >> 3;
            const int kr = kc * 16 + (lane & 7) + ((g & 1) ? 8 : 0);
            const int nf = (g & 2) ? 8 : 0;
#pragma unroll
            for (int np = 0; np < 4; np++) {
                const uint32_t off = (uint32_t)kr * 144 + (uint32_t)(np * 16 + nf) * 2;
                LDSM4T(&vh_[np * 2][0], sVh + off);
                LDSM4T(&vl_[np * 2][0], sVl + off);
            }
#pragma unroll
            for (int nt = 0; nt < 8; nt++) {
                MMA_BF16(o[nt], ph, vh_[nt]);
                MMA_BF16(o[nt], ph, vl_[nt]);
                MMA_BF16(o[nt], pl, vh_[nt]);
            }
        }

        __syncthreads();
        if (it < 30) {
            load_kv(it + 2, it & 1);
            CP_WAIT(1);
        } else {
            CP_WAIT(0);
        }
        __syncthreads();
    }

    // ---- epilogue: att as bf16 hi/lo, row-major [M][768] ----
#pragma unroll
    for (int hh = 0; hh < 2; hh++) {
        const float inv = 1.f / l_run[hh];
        const size_t m = (size_t)b * SEQ + qb + w * 16 + (lane >> 2) + hh * 8;
#pragma unroll
        for (int nt = 0; nt < 8; nt++) {
            const int col = h * 64 + nt * 8 + (lane & 3) * 2;
            uint32_t hp, lp;
            cvt_hilo(o[nt][2 * hh] * inv, o[nt][2 * hh + 1] * inv, hp, lp);
            const size_t oi = (m * D_MODEL + col) >> 1;
            ((uint32_t*)ath)[oi] = hp;
            ((uint32_t*)atl)[oi] = lp;
        }
    }
}

// ---------------------------------------------------------------------------
// LayerNorm over last dim (768)
// ---------------------------------------------------------------------------
__global__ __launch_bounds__(256) void ln_kernel(
    const float* __restrict__ x, const float* __restrict__ gamma,
    const float* __restrict__ beta, float* __restrict__ out)
{
    const int row = blockIdx.x;
    const float* xr = x + (size_t)row * D_MODEL;
    const int tid = threadIdx.x;

    float v[3];
    float s = 0.f, s2 = 0.f;
#pragma unroll
    for (int i = 0; i < 3; i++) {
        v[i] = xr[tid + i * 256];
        s += v[i];
        s2 += v[i] * v[i];
    }
#pragma unroll
    for (int off = 16; off; off >>= 1) {
        s  += __shfl_xor_sync(0xffffffffu, s,  off);
        s2 += __shfl_xor_sync(0xffffffffu, s2, off);
    }
    __shared__ float rs[8], rs2[8];
    __shared__ float mu_s, rstd_s;
    const int w = tid >> 5;
    if ((tid & 31) == 0) { rs[w] = s; rs2[w] = s2; }
    __syncthreads();
    if (tid == 0) {
        float a = 0.f, bq = 0.f;
#pragma unroll
        for (int i = 0; i < 8; i++) { a += rs[i]; bq += rs2[i]; }
        float mu = a * (1.f / D_MODEL);
        float var = bq * (1.f / D_MODEL) - mu * mu;
        mu_s = mu;
        rstd_s = rsqrtf(var + 1e-5f);
    }
    __syncthreads();
    const float mu = mu_s, rstd = rstd_s;
#pragma unroll
    for (int i = 0; i < 3; i++) {
        int c = tid + i * 256;
        out[(size_t)row * D_MODEL + c] = (v[i] - mu) * rstd * gamma[c] + beta[c];
    }
}

// ---------------------------------------------------------------------------
// kernel_launch — inputs: Q, W_q, b_q, W_k, b_k, W_v, b_v, W_o, b_o,
//                         ln_gamma, ln_beta
// ---------------------------------------------------------------------------
extern "C" void kernel_launch(void* const* d_in, const int* in_sizes, int n_in,
                              void* d_out, int out_size)
{
    const float* X     = (const float*)d_in[0];
    const float* Wq    = (const float*)d_in[1];
    const float* bq    = (const float*)d_in[2];
    const float* Wk    = (const float*)d_in[3];
    const float* bk    = (const float*)d_in[4];
    const float* Wv    = (const float*)d_in[5];
    const float* bv    = (const float*)d_in[6];
    const float* Wo    = (const float*)d_in[7];
    const float* bo    = (const float*)d_in[8];
    const float* gamma = (const float*)d_in[9];
    const float* beta  = (const float*)d_in[10];
    float* out = (float*)d_out;

    const int M = in_sizes[0] / D_MODEL;   // 4096
    const int B = M / SEQ;                 // 2

    __nv_bfloat16 *xh, *xl, *wh, *wl, *qh, *ql, *kh, *kl, *vh, *vl, *ath, *atl;
    float* x;
    cudaGetSymbolAddress((void**)&xh, g_xh);  cudaGetSymbolAddress((void**)&xl, g_xl);
    cudaGetSymbolAddress((void**)&wh, g_wh);  cudaGetSymbolAddress((void**)&wl, g_wl);
    cudaGetSymbolAddress((void**)&qh, g_qh);  cudaGetSymbolAddress((void**)&ql, g_ql);
    cudaGetSymbolAddress((void**)&kh, g_kh);  cudaGetSymbolAddress((void**)&kl, g_kl);
    cudaGetSymbolAddress((void**)&vh, g_vh);  cudaGetSymbolAddress((void**)&vl, g_vl);
    cudaGetSymbolAddress((void**)&ath, g_ath); cudaGetSymbolAddress((void**)&atl, g_atl);
    cudaGetSymbolAddress((void**)&x, g_x);

    cudaFuncSetAttribute((const void*)gemm_bs<0>,
                         cudaFuncAttributeMaxDynamicSharedMemorySize, G_SMEM);
    cudaFuncSetAttribute((const void*)gemm_bs<1>,
                         cudaFuncAttributeMaxDynamicSharedMemorySize, G_SMEM);
    cudaFuncSetAttribute((const void*)attn_bs,
                         cudaFuncAttributeMaxDynamicSharedMemorySize, A_SMEM);

    // 1) one merged split pass
    SplitSrcs ss;
    ss.p[0] = X; ss.p[1] = Wq; ss.p[2] = Wk; ss.p[3] = Wv; ss.p[4] = Wo;
    split_all<<<1184, 256>>>(ss, xh, xl, wh, wl);

    // 2) merged QKV projection (z = 0,1,2) -> head-major bf16 hi/lo
    {
        GemmAux aux;
        aux.bias[0] = bq; aux.bias[1] = bk; aux.bias[2] = bv;
        aux.oh[0] = qh; aux.oh[1] = kh; aux.oh[2] = vh;
        aux.ol[0] = ql; aux.ol[1] = kl; aux.ol[2] = vl;
        aux.R = nullptr; aux.C = nullptr;
        gemm_bs<1><<<dim3(D_MODEL / 128, M / 128, 3), 256, G_SMEM>>>(
            xh, xl, wh, wl, aux);
    }

    // 3) attention -> att bf16 hi/lo
    attn_bs<<<dim3(SEQ / 64, NHEADS, B), 128, A_SMEM>>>(qh, ql, kh, kl, vh, vl,
                                                        ath, atl);

    // 4) O-projection + residual -> fp32 x
    {
        GemmAux aux;
        aux.bias[0] = bo; aux.bias[1] = bo; aux.bias[2] = bo;
        aux.oh[0] = aux.oh[1] = aux.oh[2] = nullptr;
        aux.ol[0] = aux.ol[1] = aux.ol[2] = nullptr;
        aux.R = X; aux.C = x;
        gemm_bs<0><<<dim3(D_MODEL / 128, M / 128, 1), 256, G_SMEM>>>(
            ath, atl, wh + 3 * (size_t)WSZ, wl + 3 * (size_t)WSZ, aux);
    }

    // 5) LayerNorm
    ln_kernel<<<M, 256>>>(x, gamma, beta, out);
}

// round 8
// speedup vs baseline: 3.6049x; 1.1697x over previous
#include <cuda_runtime.h>
#include <cuda_bf16.h>
#include <cstdint>

// ---------------------------------------------------------------------------
// Problem constants
// ---------------------------------------------------------------------------
#define D_MODEL 768
#define SEQ     2048
#define NHEADS  12
#define DH      64
#define MROWS   (2 * SEQ)
#define WSZ     (D_MODEL * D_MODEL)

// ---------------------------------------------------------------------------
// Global scratch (allocation-free rule)
// ---------------------------------------------------------------------------
__device__ __nv_bfloat16 g_xh[MROWS * D_MODEL], g_xl[MROWS * D_MODEL];
__device__ __nv_bfloat16 g_wh[4 * WSZ],        g_wl[4 * WSZ];
// head-major [h][m][64] bf16
__device__ __nv_bfloat16 g_qh[NHEADS * MROWS * DH], g_ql[NHEADS * MROWS * DH];
__device__ __nv_bfloat16 g_kh[NHEADS * MROWS * DH], g_kl[NHEADS * MROWS * DH];
__device__ __nv_bfloat16 g_vh[NHEADS * MROWS * DH], g_vl[NHEADS * MROWS * DH];
__device__ __nv_bfloat16 g_ath[MROWS * D_MODEL], g_atl[MROWS * D_MODEL];
__device__ float g_x[MROWS * D_MODEL];

// ---------------------------------------------------------------------------
// PTX helpers
// ---------------------------------------------------------------------------
__device__ __forceinline__ uint32_t smem_u32(const void* p) {
    uint32_t a;
    asm("{ .reg .u64 t; cvta.to.shared.u64 t, %1; cvt.u32.u64 %0, t; }"
        : "=r"(a) : "l"(p));
    return a;
}

#define MMA_BF16(d, a, b) \
    asm volatile("mma.sync.aligned.m16n8k16.row.col.f32.bf16.bf16.f32 " \
        "{%0,%1,%2,%3}, {%4,%5,%6,%7}, {%8,%9}, {%0,%1,%2,%3};" \
        : "+f"((d)[0]), "+f"((d)[1]), "+f"((d)[2]), "+f"((d)[3]) \
        : "r"((a)[0]), "r"((a)[1]), "r"((a)[2]), "r"((a)[3]), \
          "r"((b)[0]), "r"((b)[1]))

#define LDSM4(r, addr) \
    asm volatile("ldmatrix.sync.aligned.m8n8.x4.shared.b16 {%0,%1,%2,%3}, [%4];" \
        : "=r"((r)[0]), "=r"((r)[1]), "=r"((r)[2]), "=r"((r)[3]) : "r"(addr))

#define LDSM4T(r, addr) \
    asm volatile("ldmatrix.sync.aligned.m8n8.x4.trans.shared.b16 {%0,%1,%2,%3}, [%4];" \
        : "=r"((r)[0]), "=r"((r)[1]), "=r"((r)[2]), "=r"((r)[3]) : "r"(addr))

#define CP16(dst, src) \
    asm volatile("cp.async.cg.shared.global [%0], [%1], 16;" \
                 :: "r"(dst), "l"(src))
#define CP_COMMIT() asm volatile("cp.async.commit_group;" ::: "memory")
#define CP_WAIT(N)  asm volatile("cp.async.wait_group %0;" :: "n"(N) : "memory")

// swizzles: rows of 64B (GEMM) and 128B (attention); conflict-free ldmatrix
#define SW64(off)  ((off) ^ (((off) >> 3) & 0x30))
#define SW128(off) ((off) ^ (((off) >> 3) & 0x70))

// split (x,y) fp32 -> packed bf16 hi pair (lo16=x) and lo residual pair
__device__ __forceinline__ void cvt_hilo(float x, float y, uint32_t& h2, uint32_t& l2) {
    uint32_t h;
    asm("cvt.rn.bf16x2.f32 %0, %1, %2;" : "=r"(h) : "f"(y), "f"(x));
    float hx = __uint_as_float(h << 16);
    float hy = __uint_as_float(h & 0xffff0000u);
    uint32_t l;
    float lx = x - hx, ly = y - hy;
    asm("cvt.rn.bf16x2.f32 %0, %1, %2;" : "=r"(l) : "f"(ly), "f"(lx));
    h2 = h; l2 = l;
}

// ---------------------------------------------------------------------------
// One merged split pass: X and the four weights -> bf16 hi/lo
// ---------------------------------------------------------------------------
struct SplitSrcs { const float* p[5]; };

#define NX4 (MROWS * D_MODEL / 4)   // 786432
#define NW4 (WSZ / 4)               // 147456

__global__ void split_all(SplitSrcs s,
                          __nv_bfloat16* __restrict__ xh, __nv_bfloat16* __restrict__ xl,
                          __nv_bfloat16* __restrict__ wh, __nv_bfloat16* __restrict__ wl)
{
    const int total = NX4 + 4 * NW4;
    for (int i = blockIdx.x * blockDim.x + threadIdx.x; i < total;
         i += gridDim.x * blockDim.x) {
        int seg, off;
        if (i < NX4) { seg = 0; off = i; }
        else { const int j = i - NX4; seg = 1 + j / NW4; off = j - (seg - 1) * NW4; }
        const float4 v = ((const float4*)s.p[seg])[off];
        uint32_t h0, l0, h1, l1;
        cvt_hilo(v.x, v.y, h0, l0);
        cvt_hilo(v.z, v.w, h1, l1);
        uint32_t* dh;
        uint32_t* dl;
        if (seg == 0) { dh = (uint32_t*)xh; dl = (uint32_t*)xl; }
        else {
            dh = (uint32_t*)(wh + (size_t)(seg - 1) * WSZ);
            dl = (uint32_t*)(wl + (size_t)(seg - 1) * WSZ);
        }
        dh[2 * off] = h0; dh[2 * off + 1] = h1;
        dl[2 * off] = l0; dl[2 * off + 1] = l1;
    }
}

// ---------------------------------------------------------------------------
// GEMM on pre-split hi/lo bf16 (3-MMA fp32 emulation).
// CTA tile 128 x NTILE, BK=32, 3-stage cp.async ring (1 sync/iter), 8 warps.
// Swizzled SW64 smem, 64B rows. 2 CTAs/SM.
// MODE 0 (NTILE=64): O-proj -> fp32 C = acc + bias + R
// MODE 1 (NTILE=128): QKV   -> head-major bf16 hi/lo, z picks W/bias/out
// ---------------------------------------------------------------------------
#define G_ATIL 8192

struct GemmAux {
    const float* bias[3];
    __nv_bfloat16* oh[3];
    __nv_bfloat16* ol[3];
    const float* R;
    float* C;
};

template <int MODE, int NTILE>
__global__ __launch_bounds__(256, 2) void gemm_bs(
    const __nv_bfloat16* __restrict__ Ah, const __nv_bfloat16* __restrict__ Al,
    const __nv_bfloat16* __restrict__ WhB, const __nv_bfloat16* __restrict__ WlB,
    GemmAux aux)
{
    constexpr int B_TIL = NTILE * 64;
    constexpr int STAGE = 2 * G_ATIL + 2 * B_TIL;
    constexpr int WN = NTILE / 2;      // per-warp N
    constexpr int NT = WN / 8;         // n-frags per warp
    constexpr int NCHUNK = (2 * 128 + 2 * NTILE) * 4;  // 16B chunks per stage
    constexpr int PERTHR = NCHUNK / 256;

    extern __shared__ char sm[];
    const uint32_t sb = smem_u32(sm);
    const int tid = threadIdx.x;
    const int lane = tid & 31;
    const int warp = tid >> 5;
    const int wm = warp >> 1;
    const int wn = warp & 1;
    const int bm = blockIdx.y * 128;
    const int bn = blockIdx.x * NTILE;
    const int z = (MODE == 1) ? blockIdx.z : 0;

    const __nv_bfloat16* Bh = WhB + (size_t)z * WSZ;
    const __nv_bfloat16* Bl = WlB + (size_t)z * WSZ;
    const float* bias = aux.bias[z];

    const __nv_bfloat16* tsrc[4] = {Ah, Al, Bh, Bl};

    auto load_stage = [&](int kt, int st) {
        const uint32_t dst0 = sb + st * STAGE;
#pragma unroll
        for (int i = 0; i < PERTHR; i++) {
            const int c = tid + i * 256;
            int t, r, toff;
            if (c < 2 * 512) {                   // A hi/lo: 512 chunks each
                t = c >> 9; r = (c >> 2) & 127; toff = t * G_ATIL;
            } else {
                const int j = c - 1024;
                t = 2 + j / (NTILE * 4);
                r = (j >> 2) % NTILE;
                toff = 2 * G_ATIL + (t - 2) * B_TIL;
            }
            const int ch = c & 3;
            const int grow = ((t < 2) ? bm : bn) + r;
            const char* src = (const char*)(tsrc[t] + (size_t)grow * D_MODEL + kt * 32)
                            + ch * 16;
            const uint32_t off = (uint32_t)r * 64 + (uint32_t)ch * 16;
            CP16(dst0 + toff + SW64(off), src);
        }
        CP_COMMIT();
    };

    load_stage(0, 0);
    load_stage(1, 1);
    CP_WAIT(1);
    __syncthreads();

    float acc[2][NT][4];
#pragma unroll
    for (int mt = 0; mt < 2; mt++)
#pragma unroll
        for (int nt = 0; nt < NT; nt++)
#pragma unroll
            for (int c = 0; c < 4; c++) acc[mt][nt][c] = 0.f;

    int cur = 0, isl = 2;
    for (int kt = 0; kt < 24; kt++) {
        if (kt < 22) {
            load_stage(kt + 2, isl);
            isl = (isl == 2) ? 0 : isl + 1;
        }
        const uint32_t sA = sb + cur * STAGE;
        cur = (cur == 2) ? 0 : cur + 1;

#pragma unroll
        for (int ks = 0; ks < 2; ks++) {
            uint32_t ah[2][4], al[2][4];
#pragma unroll
            for (int mt = 0; mt < 2; mt++) {
                const int r = wm * 32 + mt * 16 + (lane & 15);
                const uint32_t off = SW64((uint32_t)r * 64
                                    + (uint32_t)(ks * 2 + (lane >> 4)) * 16);
                LDSM4(ah[mt], sA + off);
                LDSM4(al[mt], sA + G_ATIL + off);
            }
#pragma unroll
            for (int qg = 0; qg < NT / 4; qg++) {
                uint32_t bh[4][2], bl[4][2];
                const int g = lane >> 3;
                const int rb = wn * WN + qg * 32 + (lane & 7) + ((g & 2) ? 8 : 0);
                const int cc = ks * 2 + (g & 1);
#pragma unroll
                for (int np = 0; np < 2; np++) {
                    const int r = rb + np * 16;
                    const uint32_t off = SW64((uint32_t)r * 64 + (uint32_t)cc * 16);
                    LDSM4(&bh[np * 2][0], sA + 2 * G_ATIL + off);
                    LDSM4(&bl[np * 2][0], sA + 2 * G_ATIL + B_TIL + off);
                }
#pragma unroll
                for (int mt = 0; mt < 2; mt++)
#pragma unroll
                    for (int n4 = 0; n4 < 4; n4++) {
                        const int nt = qg * 4 + n4;
                        MMA_BF16(acc[mt][nt], ah[mt], bh[n4]);
                        MMA_BF16(acc[mt][nt], ah[mt], bl[n4]);
                        MMA_BF16(acc[mt][nt], al[mt], bh[n4]);
                    }
            }
        }
        if (kt < 22) { CP_WAIT(1); } else { CP_WAIT(0); }
        __syncthreads();
    }

    // epilogue
    const float scale = (MODE == 1 && z == 0) ? 0.125f : 1.0f;
#pragma unroll
    for (int mt = 0; mt < 2; mt++)
#pragma unroll
        for (int hh = 0; hh < 2; hh++) {
            const int m = bm + wm * 32 + mt * 16 + (lane >> 2) + hh * 8;
#pragma unroll
            for (int nt = 0; nt < NT; nt++) {
                const int col = bn + wn * WN + nt * 8 + (lane & 3) * 2;
                float x0 = acc[mt][nt][2 * hh]     + bias[col];
                float x1 = acc[mt][nt][2 * hh + 1] + bias[col + 1];
                if (MODE == 0) {
                    const float2 rr = *(const float2*)(aux.R + (size_t)m * D_MODEL + col);
                    float2 v = {x0 + rr.x, x1 + rr.y};
                    *(float2*)(aux.C + (size_t)m * D_MODEL + col) = v;
                } else {
                    x0 *= scale; x1 *= scale;
                    uint32_t hp, lp;
                    cvt_hilo(x0, x1, hp, lp);
                    const int hd = col >> 6;
                    const int dh = col & 63;
                    const size_t oi = ((size_t)hd * MROWS + m) * 32 + (dh >> 1);
                    ((uint32_t*)aux.oh[z])[oi] = hp;
                    ((uint32_t*)aux.ol[z])[oi] = lp;
                }
            }
        }
}

// ---------------------------------------------------------------------------
// Flash attention on pre-split head-major bf16 hi/lo q/k/v.
// CTA = 128 threads (4 warps), 64 q rows; warp-private softmax.
// KV tiles of 64 keys, 3-stage cp.async ring (1 sync/iter), SW128 smem.
// smem: Q 2x8192 + 3 KV stages x 32768 = 114688 B ; 2 CTAs/SM.
// ---------------------------------------------------------------------------
#define AQ_TIL 8192
#define AKV0   16384
#define AKV_T  8192
#define AKV_S  32768
#define A_SMEM (AKV0 + 3 * AKV_S)   // 114688

__global__ __launch_bounds__(128) void attn_bs(
    const __nv_bfloat16* __restrict__ qh_g, const __nv_bfloat16* __restrict__ ql_g,
    const __nv_bfloat16* __restrict__ kh_g, const __nv_bfloat16* __restrict__ kl_g,
    const __nv_bfloat16* __restrict__ vh_g, const __nv_bfloat16* __restrict__ vl_g,
    __nv_bfloat16* __restrict__ ath, __nv_bfloat16* __restrict__ atl)
{
    extern __shared__ char sm[];
    const uint32_t sb = smem_u32(sm);
    const int tid = threadIdx.x;
    const int lane = tid & 31;
    const int w = tid >> 5;
    const int qb = blockIdx.x * 64;
    const int h = blockIdx.y;
    const int b = blockIdx.z;
    const size_t hq = (size_t)h * MROWS + (size_t)b * SEQ;

    const __nv_bfloat16* kvsrc[4] = {kh_g, kl_g, vh_g, vl_g};

    // Q loads (join first commit group): 2 tiles x 64 rows x 8 chunks
    {
#pragma unroll
        for (int i = 0; i < 8; i++) {
            const int c = tid + i * 128;
            const int t = c >> 9;
            const int r = (c >> 3) & 63;
            const int ch = c & 7;
            const char* src = (const char*)((t ? ql_g : qh_g) + (hq + qb + r) * DH)
                            + ch * 16;
            const uint32_t off = SW128((uint32_t)r * 128 + (uint32_t)ch * 16);
            CP16(sb + t * AQ_TIL + off, src);
        }
    }

    auto load_kv = [&](int it, int st) {
        const int kv = it * 64;
        const uint32_t dst0 = sb + AKV0 + st * AKV_S;
#pragma unroll
        for (int i = 0; i < 16; i++) {
            const int c = tid + i * 128;
            const int t = c >> 9;
            const int r = (c >> 3) & 63;
            const int ch = c & 7;
            const char* src = (const char*)(kvsrc[t] + (hq + kv + r) * DH) + ch * 16;
            const uint32_t off = SW128((uint32_t)r * 128 + (uint32_t)ch * 16);
            CP16(dst0 + t * AKV_T + off, src);
        }
        CP_COMMIT();
    };

    load_kv(0, 0);       // group 0 = Q + kv0
    load_kv(1, 1);       // group 1 = kv1
    CP_WAIT(1);          // Q + kv0 ready
    __syncthreads();

    // hoist Q fragments (reused all 32 iterations)
    uint32_t qfh[4][4], qfl[4][4];
#pragma unroll
    for (int ks = 0; ks < 4; ks++) {
        const int r = w * 16 + (lane & 15);
        const uint32_t off = SW128((uint32_t)r * 128
                            + (uint32_t)(ks * 2 + (lane >> 4)) * 16);
        LDSM4(qfh[ks], sb + off);
        LDSM4(qfl[ks], sb + AQ_TIL + off);
    }

    float o[8][4];
    float m_run[2] = {-1e30f, -1e30f}, l_run[2] = {0.f, 0.f};
#pragma unroll
    for (int nt = 0; nt < 8; nt++)
#pragma unroll
        for (int c = 0; c < 4; c++) o[nt][c] = 0.f;

    int cur = 0, isl = 2;
    for (int it = 0; it < 32; it++) {
        if (it < 30) {
            load_kv(it + 2, isl);
            isl = (isl == 2) ? 0 : isl + 1;
        }
        const uint32_t sKh = sb + AKV0 + cur * AKV_S;
        const uint32_t sKl = sKh + AKV_T;
        const uint32_t sVh = sKh + 2 * AKV_T;
        const uint32_t sVl = sKh + 3 * AKV_T;
        cur = (cur == 2) ? 0 : cur + 1;

        // ---- S = Q K^T  (16 q x 64 keys) ----
        float s[8][4];
#pragma unroll
        for (int nt = 0; nt < 8; nt++)
#pragma unroll
            for (int c = 0; c < 4; c++) s[nt][c] = 0.f;

#pragma unroll
        for (int ks = 0; ks < 4; ks++) {
            uint32_t kh_[8][2], kl_[8][2];
            const int g = lane >> 3;
            const int nr = (lane & 7) + ((g & 2) ? 8 : 0);
            const int cc = ks * 2 + (g & 1);
#pragma unroll
            for (int np = 0; np < 4; np++) {
                const int r = nr + np * 16;
                const uint32_t off = SW128((uint32_t)r * 128 + (uint32_t)cc * 16);
                LDSM4(&kh_[np * 2][0], sKh + off);
                LDSM4(&kl_[np * 2][0], sKl + off);
            }
#pragma unroll
            for (int nt = 0; nt < 8; nt++) {
                MMA_BF16(s[nt], qfh[ks], kh_[nt]);
                MMA_BF16(s[nt], qfh[ks], kl_[nt]);
                MMA_BF16(s[nt], qfl[ks], kh_[nt]);
            }
        }

        // ---- warp-private online softmax (2 rows per thread) ----
        float corr[2];
#pragma unroll
        for (int hh = 0; hh < 2; hh++) {
            float m = -1e30f;
#pragma unroll
            for (int nt = 0; nt < 8; nt++)
                m = fmaxf(m, fmaxf(s[nt][2 * hh], s[nt][2 * hh + 1]));
            m = fmaxf(m, __shfl_xor_sync(0xffffffffu, m, 1));
            m = fmaxf(m, __shfl_xor_sync(0xffffffffu, m, 2));
            const float mn = fmaxf(m_run[hh], m);
            corr[hh] = __expf(m_run[hh] - mn);
            m_run[hh] = mn;
        }
        float ps[2] = {0.f, 0.f};
#pragma unroll
        for (int nt = 0; nt < 8; nt++)
#pragma unroll
            for (int c = 0; c < 4; c++) {
                const float p = __expf(s[nt][c] - m_run[c >> 1]);
                s[nt][c] = p;
                ps[c >> 1] += p;
            }
#pragma unroll
        for (int hh = 0; hh < 2; hh++) {
            float v = ps[hh];
            v += __shfl_xor_sync(0xffffffffu, v, 1);
            v += __shfl_xor_sync(0xffffffffu, v, 2);
            l_run[hh] = l_run[hh] * corr[hh] + v;
        }
#pragma unroll
        for (int nt = 0; nt < 8; nt++)
#pragma unroll
            for (int c = 0; c < 4; c++) o[nt][c] *= corr[c >> 1];

        // ---- O += P V (register P hi/lo, ldmatrix.trans V) ----
#pragma unroll
        for (int kc = 0; kc < 4; kc++) {
            uint32_t ph[4], pl[4];
            cvt_hilo(s[2 * kc][0],     s[2 * kc][1],     ph[0], pl[0]);
            cvt_hilo(s[2 * kc][2],     s[2 * kc][3],     ph[1], pl[1]);
            cvt_hilo(s[2 * kc + 1][0], s[2 * kc + 1][1], ph[2], pl[2]);
            cvt_hilo(s[2 * kc + 1][2], s[2 * kc + 1][3], ph[3], pl[3]);
            uint32_t vh_[8][2], vl_[8][2];
            const int g = lane >> 3;
            const int kr = kc * 16 + (lane & 7) + ((g & 1) ? 8 : 0);
            const int nf = (g & 2) ? 8 : 0;
#pragma unroll
            for (int np = 0; np < 4; np++) {
                const int cc = np * 2 + (nf >> 3);
                const uint32_t off = SW128((uint32_t)kr * 128 + (uint32_t)cc * 16);
                LDSM4T(&vh_[np * 2][0], sVh + off);
                LDSM4T(&vl_[np * 2][0], sVl + off);
            }
#pragma unroll
            for (int nt = 0; nt < 8; nt++) {
                MMA_BF16(o[nt], ph, vh_[nt]);
                MMA_BF16(o[nt], ph, vl_[nt]);
                MMA_BF16(o[nt], pl, vh_[nt]);
            }
        }

        if (it < 30) { CP_WAIT(1); } else { CP_WAIT(0); }
        __syncthreads();
    }

    // ---- epilogue: att as bf16 hi/lo, row-major [M][768] ----
#pragma unroll
    for (int hh = 0; hh < 2; hh++) {
        const float inv = 1.f / l_run[hh];
        const size_t m = (size_t)b * SEQ + qb + w * 16 + (lane >> 2) + hh * 8;
#pragma unroll
        for (int nt = 0; nt < 8; nt++) {
            const int col = h * 64 + nt * 8 + (lane & 3) * 2;
            uint32_t hp, lp;
            cvt_hilo(o[nt][2 * hh] * inv, o[nt][2 * hh + 1] * inv, hp, lp);
            const size_t oi = (m * D_MODEL + col) >> 1;
            ((uint32_t*)ath)[oi] = hp;
            ((uint32_t*)atl)[oi] = lp;
        }
    }
}

// ---------------------------------------------------------------------------
// LayerNorm over last dim (768)
// ---------------------------------------------------------------------------
__global__ __launch_bounds__(256) void ln_kernel(
    const float* __restrict__ x, const float* __restrict__ gamma,
    const float* __restrict__ beta, float* __restrict__ out)
{
    const int row = blockIdx.x;
    const float* xr = x + (size_t)row * D_MODEL;
    const int tid = threadIdx.x;

    float v[3];
    float s = 0.f, s2 = 0.f;
#pragma unroll
    for (int i = 0; i < 3; i++) {
        v[i] = xr[tid + i * 256];
        s += v[i];
        s2 += v[i] * v[i];
    }
#pragma unroll
    for (int off = 16; off; off >>= 1) {
        s  += __shfl_xor_sync(0xffffffffu, s,  off);
        s2 += __shfl_xor_sync(0xffffffffu, s2, off);
    }
    __shared__ float rs[8], rs2[8];
    __shared__ float mu_s, rstd_s;
    const int w = tid >> 5;
    if ((tid & 31) == 0) { rs[w] = s; rs2[w] = s2; }
    __syncthreads();
    if (tid == 0) {
        float a = 0.f, bq = 0.f;
#pragma unroll
        for (int i = 0; i < 8; i++) { a += rs[i]; bq += rs2[i]; }
        float mu = a * (1.f / D_MODEL);
        float var = bq * (1.f / D_MODEL) - mu * mu;
        mu_s = mu;
        rstd_s = rsqrtf(var + 1e-5f);
    }
    __syncthreads();
    const float mu = mu_s, rstd = rstd_s;
#pragma unroll
    for (int i = 0; i < 3; i++) {
        int c = tid + i * 256;
        out[(size_t)row * D_MODEL + c] = (v[i] - mu) * rstd * gamma[c] + beta[c];
    }
}

// ---------------------------------------------------------------------------
// kernel_launch — inputs: Q, W_q, b_q, W_k, b_k, W_v, b_v, W_o, b_o,
//                         ln_gamma, ln_beta
// ---------------------------------------------------------------------------
extern "C" void kernel_launch(void* const* d_in, const int* in_sizes, int n_in,
                              void* d_out, int out_size)
{
    const float* X     = (const float*)d_in[0];
    const float* Wq    = (const float*)d_in[1];
    const float* bq    = (const float*)d_in[2];
    const float* Wk    = (const float*)d_in[3];
    const float* bk    = (const float*)d_in[4];
    const float* Wv    = (const float*)d_in[5];
    const float* bv    = (const float*)d_in[6];
    const float* Wo    = (const float*)d_in[7];
    const float* bo    = (const float*)d_in[8];
    const float* gamma = (const float*)d_in[9];
    const float* beta  = (const float*)d_in[10];
    float* out = (float*)d_out;

    const int M = in_sizes[0] / D_MODEL;   // 4096
    const int B = M / SEQ;                 // 2

    __nv_bfloat16 *xh, *xl, *wh, *wl, *qh, *ql, *kh, *kl, *vh, *vl, *ath, *atl;
    float* x;
    cudaGetSymbolAddress((void**)&xh, g_xh);  cudaGetSymbolAddress((void**)&xl, g_xl);
    cudaGetSymbolAddress((void**)&wh, g_wh);  cudaGetSymbolAddress((void**)&wl, g_wl);
    cudaGetSymbolAddress((void**)&qh, g_qh);  cudaGetSymbolAddress((void**)&ql, g_ql);
    cudaGetSymbolAddress((void**)&kh, g_kh);  cudaGetSymbolAddress((void**)&kl, g_kl);
    cudaGetSymbolAddress((void**)&vh, g_vh);  cudaGetSymbolAddress((void**)&vl, g_vl);
    cudaGetSymbolAddress((void**)&ath, g_ath); cudaGetSymbolAddress((void**)&atl, g_atl);
    cudaGetSymbolAddress((void**)&x, g_x);

    constexpr int G_SMEM_128 = 3 * (2 * G_ATIL + 2 * 128 * 64);  // 98304
    constexpr int G_SMEM_64  = 3 * (2 * G_ATIL + 2 * 64 * 64);   // 73728

    cudaFuncSetAttribute((const void*)gemm_bs<1, 128>,
                         cudaFuncAttributeMaxDynamicSharedMemorySize, G_SMEM_128);
    cudaFuncSetAttribute((const void*)gemm_bs<0, 64>,
                         cudaFuncAttributeMaxDynamicSharedMemorySize, G_SMEM_64);
    cudaFuncSetAttribute((const void*)attn_bs,
                         cudaFuncAttributeMaxDynamicSharedMemorySize, A_SMEM);

    // 1) one merged split pass
    SplitSrcs ss;
    ss.p[0] = X; ss.p[1] = Wq; ss.p[2] = Wk; ss.p[3] = Wv; ss.p[4] = Wo;
    split_all<<<1184, 256>>>(ss, xh, xl, wh, wl);

    // 2) merged QKV projection (z = 0,1,2) -> head-major bf16 hi/lo
    {
        GemmAux aux;
        aux.bias[0] = bq; aux.bias[1] = bk; aux.bias[2] = bv;
        aux.oh[0] = qh; aux.oh[1] = kh; aux.oh[2] = vh;
        aux.ol[0] = ql; aux.ol[1] = kl; aux.ol[2] = vl;
        aux.R = nullptr; aux.C = nullptr;
        gemm_bs<1, 128><<<dim3(D_MODEL / 128, M / 128, 3), 256, G_SMEM_128>>>(
            xh, xl, wh, wl, aux);
    }

    // 3) attention -> att bf16 hi/lo
    attn_bs<<<dim3(SEQ / 64, NHEADS, B), 128, A_SMEM>>>(qh, ql, kh, kl, vh, vl,
                                                        ath, atl);

    // 4) O-projection + residual -> fp32 x  (128x64 tiles: 384 CTAs, balanced)
    {
        GemmAux aux;
        aux.bias[0] = bo; aux.bias[1] = bo; aux.bias[2] = bo;
        aux.oh[0] = aux.oh[1] = aux.oh[2] = nullptr;
        aux.ol[0] = aux.ol[1] = aux.ol[2] = nullptr;
        aux.R = X; aux.C = x;
        gemm_bs<0, 64><<<dim3(D_MODEL / 64, M / 128, 1), 256, G_SMEM_64>>>(
            ath, atl, wh + 3 * (size_t)WSZ, wl + 3 * (size_t)WSZ, aux);
    }

    // 5) LayerNorm
    ln_kernel<<<M, 256>>>(x, gamma, beta, out);
}

// round 11
// speedup vs baseline: 4.9631x; 1.3768x over previous
#include <cuda_runtime.h>
#include <cuda_fp16.h>
#include <cstdint>

// ---------------------------------------------------------------------------
// Problem constants
// ---------------------------------------------------------------------------
#define D_MODEL 768
#define SEQ     2048
#define NHEADS  12
#define DH      64
#define MROWS   (2 * SEQ)
#define WSZ     (D_MODEL * D_MODEL)

// ---------------------------------------------------------------------------
// Global scratch (allocation-free rule)
// X and Q split fp16 hi/lo; weights, K, V single fp16 (rounding absorbed by
// the A-side split: D = Ahi*B + Alo*B, error ~2^-13 per term).
// ---------------------------------------------------------------------------
__device__ __half g_xh[MROWS * D_MODEL], g_xl[MROWS * D_MODEL];
__device__ __half g_wf[4 * WSZ];
// head-major [h][m][64] fp16
__device__ __half g_qh[NHEADS * MROWS * DH], g_ql[NHEADS * MROWS * DH];
__device__ __half g_kf[NHEADS * MROWS * DH];
__device__ __half g_vf[NHEADS * MROWS * DH];
__device__ __half g_ath[MROWS * D_MODEL], g_atl[MROWS * D_MODEL];
__device__ float g_x[MROWS * D_MODEL];

// ---------------------------------------------------------------------------
// PTX helpers
// ---------------------------------------------------------------------------
__device__ __forceinline__ uint32_t smem_u32(const void* p) {
    uint32_t a;
    asm("{ .reg .u64 t; cvta.to.shared.u64 t, %1; cvt.u32.u64 %0, t; }"
        : "=r"(a) : "l"(p));
    return a;
}

#define MMA_F16(d, a, b) \
    asm volatile("mma.sync.aligned.m16n8k16.row.col.f32.f16.f16.f32 " \
        "{%0,%1,%2,%3}, {%4,%5,%6,%7}, {%8,%9}, {%0,%1,%2,%3};" \
        : "+f"((d)[0]), "+f"((d)[1]), "+f"((d)[2]), "+f"((d)[3]) \
        : "r"((a)[0]), "r"((a)[1]), "r"((a)[2]), "r"((a)[3]), \
          "r"((b)[0]), "r"((b)[1]))

#define LDSM4(r, addr) \
    asm volatile("ldmatrix.sync.aligned.m8n8.x4.shared.b16 {%0,%1,%2,%3}, [%4];" \
        : "=r"((r)[0]), "=r"((r)[1]), "=r"((r)[2]), "=r"((r)[3]) : "r"(addr))

#define LDSM4T(r, addr) \
    asm volatile("ldmatrix.sync.aligned.m8n8.x4.trans.shared.b16 {%0,%1,%2,%3}, [%4];" \
        : "=r"((r)[0]), "=r"((r)[1]), "=r"((r)[2]), "=r"((r)[3]) : "r"(addr))

#define CP16(dst, src) \
    asm volatile("cp.async.cg.shared.global [%0], [%1], 16;" \
                 :: "r"(dst), "l"(src))
#define CP_COMMIT() asm volatile("cp.async.commit_group;" ::: "memory")
#define CP_WAIT(N)  asm volatile("cp.async.wait_group %0;" :: "n"(N) : "memory")

// swizzles: rows of 64B (GEMM) and 128B (attention); conflict-free ldmatrix
#define SW64(off)  ((off) ^ (((off) >> 3) & 0x30))
#define SW128(off) ((off) ^ (((off) >> 3) & 0x70))

// pack (x,y) as fp16x2
__device__ __forceinline__ uint32_t cvt_f16x2(float x, float y) {
    __half2 h = __floats2half2_rn(x, y);
    return *(uint32_t*)&h;
}
// split (x,y) fp32 -> fp16 hi pair + fp16 lo residual pair
__device__ __forceinline__ void cvt_hilo16(float x, float y, uint32_t& h2, uint32_t& l2) {
    __half2 h = __floats2half2_rn(x, y);
    float2 hf = __half22float2(h);
    __half2 l = __floats2half2_rn(x - hf.x, y - hf.y);
    h2 = *(uint32_t*)&h;
    l2 = *(uint32_t*)&l;
}

// ---------------------------------------------------------------------------
// One merged split pass: X -> fp16 hi/lo ; four weights -> fp16 (rounded)
// ---------------------------------------------------------------------------
struct SplitSrcs { const float* p[5]; };

#define NX4 (MROWS * D_MODEL / 4)   // 786432
#define NW4 (WSZ / 4)               // 147456

__global__ void split_all(SplitSrcs s,
                          __half* __restrict__ xh, __half* __restrict__ xl,
                          __half* __restrict__ wf)
{
    const int total = NX4 + 4 * NW4;
    for (int i = blockIdx.x * blockDim.x + threadIdx.x; i < total;
         i += gridDim.x * blockDim.x) {
        int seg, off;
        if (i < NX4) { seg = 0; off = i; }
        else { const int j = i - NX4; seg = 1 + j / NW4; off = j - (seg - 1) * NW4; }
        const float4 v = ((const float4*)s.p[seg])[off];
        if (seg == 0) {
            uint32_t h0, l0, h1, l1;
            cvt_hilo16(v.x, v.y, h0, l0);
            cvt_hilo16(v.z, v.w, h1, l1);
            ((uint32_t*)xh)[2 * off] = h0; ((uint32_t*)xh)[2 * off + 1] = h1;
            ((uint32_t*)xl)[2 * off] = l0; ((uint32_t*)xl)[2 * off + 1] = l1;
        } else {
            uint32_t* dw = (uint32_t*)(wf + (size_t)(seg - 1) * WSZ);
            dw[2 * off]     = cvt_f16x2(v.x, v.y);
            dw[2 * off + 1] = cvt_f16x2(v.z, v.w);
        }
    }
}

// ---------------------------------------------------------------------------
// GEMM: A split fp16 hi/lo, B single fp16 (2-MMA fp32 emulation).
// CTA tile 128 x NTILE, BK=32, 3-stage cp.async ring (1 sync/iter), 8 warps.
// Swizzled SW64 smem. 2 CTAs/SM.
// MODE 0 (NTILE=64): O-proj -> fp32 C = acc + bias + R
// MODE 1 (NTILE=128): QKV -> head-major fp16; z=0 (Q) hi/lo, z=1,2 single
// ---------------------------------------------------------------------------
#define G_ATIL 8192

struct GemmAux {
    const float* bias[3];
    __half* oh[3];
    __half* ol;        // lo output for z==0 (Q) only
    const float* R;
    float* C;
};

template <int MODE, int NTILE>
__global__ __launch_bounds__(256, 2) void gemm_bs(
    const __half* __restrict__ Ah, const __half* __restrict__ Al,
    const __half* __restrict__ WfB, GemmAux aux)
{
    constexpr int B_TIL = NTILE * 64;
    constexpr int STAGE = 2 * G_ATIL + B_TIL;
    constexpr int WN = NTILE / 2;      // per-warp N
    constexpr int NT = WN / 8;         // n-frags per warp
    constexpr int NCHUNK = (2 * 128 + NTILE) * 4;  // 16B chunks per stage
    constexpr int PERTHR = NCHUNK / 256;

    extern __shared__ char sm[];
    const uint32_t sb = smem_u32(sm);
    const int tid = threadIdx.x;
    const int lane = tid & 31;
    const int warp = tid >> 5;
    const int wm = warp >> 1;
    const int wn = warp & 1;
    const int bm = blockIdx.y * 128;
    const int bn = blockIdx.x * NTILE;
    const int z = (MODE == 1) ? blockIdx.z : 0;

    const __half* Bf = WfB + (size_t)z * WSZ;
    const float* bias = aux.bias[z];

    auto load_stage = [&](int kt, int st) {
        const uint32_t dst0 = sb + st * STAGE;
#pragma unroll
        for (int i = 0; i < PERTHR; i++) {
            const int c = tid + i * 256;
            int t, r, toff;
            if (c < 1024) {                      // A hi/lo: 512 chunks each
                t = c >> 9; r = (c >> 2) & 127; toff = t * G_ATIL;
            } else {
                const int j = c - 1024;
                t = 2; r = j >> 2; toff = 2 * G_ATIL;
            }
            const int ch = c & 3;
            const int grow = ((t < 2) ? bm : bn) + r;
            const __half* base = (t == 0) ? Ah : ((t == 1) ? Al : Bf);
            const char* src = (const char*)(base + (size_t)grow * D_MODEL + kt * 32)
                            + ch * 16;
            const uint32_t off = (uint32_t)r * 64 + (uint32_t)ch * 16;
            CP16(dst0 + toff + SW64(off), src);
        }
        CP_COMMIT();
    };

    load_stage(0, 0);
    load_stage(1, 1);
    CP_WAIT(1);
    __syncthreads();

    float acc[2][NT][4];
#pragma unroll
    for (int mt = 0; mt < 2; mt++)
#pragma unroll
        for (int nt = 0; nt < NT; nt++)
#pragma unroll
            for (int c = 0; c < 4; c++) acc[mt][nt][c] = 0.f;

    int cur = 0, isl = 2;
    for (int kt = 0; kt < 24; kt++) {
        if (kt < 22) {
            load_stage(kt + 2, isl);
            isl = (isl == 2) ? 0 : isl + 1;
        }
        const uint32_t sA = sb + cur * STAGE;
        cur = (cur == 2) ? 0 : cur + 1;

#pragma unroll
        for (int ks = 0; ks < 2; ks++) {
            uint32_t ah[2][4], al[2][4];
#pragma unroll
            for (int mt = 0; mt < 2; mt++) {
                const int r = wm * 32 + mt * 16 + (lane & 15);
                const uint32_t off = SW64((uint32_t)r * 64
                                    + (uint32_t)(ks * 2 + (lane >> 4)) * 16);
                LDSM4(ah[mt], sA + off);
                LDSM4(al[mt], sA + G_ATIL + off);
            }
#pragma unroll
            for (int qg = 0; qg < NT / 4; qg++) {
                uint32_t bh[4][2];
                const int g = lane >> 3;
                const int rb = wn * WN + qg * 32 + (lane & 7) + ((g & 2) ? 8 : 0);
                const int cc = ks * 2 + (g & 1);
#pragma unroll
                for (int np = 0; np < 2; np++) {
                    const int r = rb + np * 16;
                    const uint32_t off = SW64((uint32_t)r * 64 + (uint32_t)cc * 16);
                    LDSM4(&bh[np * 2][0], sA + 2 * G_ATIL + off);
                }
#pragma unroll
                for (int mt = 0; mt < 2; mt++)
#pragma unroll
                    for (int n4 = 0; n4 < 4; n4++) {
                        const int nt = qg * 4 + n4;
                        MMA_F16(acc[mt][nt], ah[mt], bh[n4]);
                        MMA_F16(acc[mt][nt], al[mt], bh[n4]);
                    }
            }
        }
        if (kt < 22) { CP_WAIT(1); } else { CP_WAIT(0); }
        __syncthreads();
    }

    // epilogue
    const float scale = (MODE == 1 && z == 0) ? 0.125f : 1.0f;
#pragma unroll
    for (int mt = 0; mt < 2; mt++)
#pragma unroll
        for (int hh = 0; hh < 2; hh++) {
            const int m = bm + wm * 32 + mt * 16 + (lane >> 2) + hh * 8;
#pragma unroll
            for (int nt = 0; nt < NT; nt++) {
                const int col = bn + wn * WN + nt * 8 + (lane & 3) * 2;
                float x0 = acc[mt][nt][2 * hh]     + bias[col];
                float x1 = acc[mt][nt][2 * hh + 1] + bias[col + 1];
                if (MODE == 0) {
                    const float2 rr = *(const float2*)(aux.R + (size_t)m * D_MODEL + col);
                    float2 v = {x0 + rr.x, x1 + rr.y};
                    *(float2*)(aux.C + (size_t)m * D_MODEL + col) = v;
                } else {
                    x0 *= scale; x1 *= scale;
                    const int hd = col >> 6;
                    const int dh = col & 63;
                    const size_t oi = ((size_t)hd * MROWS + m) * 32 + (dh >> 1);
                    if (z == 0) {
                        uint32_t hp, lp;
                        cvt_hilo16(x0, x1, hp, lp);
                        ((uint32_t*)aux.oh[0])[oi] = hp;
                        ((uint32_t*)aux.ol)[oi] = lp;
                    } else {
                        ((uint32_t*)aux.oh[z])[oi] = cvt_f16x2(x0, x1);
                    }
                }
            }
        }
}

// ---------------------------------------------------------------------------
// Flash attention: Q split fp16 hi/lo, K/V single fp16 (2-MMA emulation;
// P split in-register). CTA = 128 threads (4 warps), 64 q rows.
// KV tiles of 64 keys, 3-stage cp.async ring, SW128 smem.
// smem: Q 2x8192 + 3 KV stages x 16384 = 65536 B ; 3 CTAs/SM.
// ---------------------------------------------------------------------------
#define AQ_TIL 8192
#define AKV0   16384
#define AKV_T  8192
#define AKV_S  16384
#define A_SMEM (AKV0 + 3 * AKV_S)   // 65536

__global__ __launch_bounds__(128, 3) void attn_bs(
    const __half* __restrict__ qh_g, const __half* __restrict__ ql_g,
    const __half* __restrict__ kf_g, const __half* __restrict__ vf_g,
    __half* __restrict__ ath, __half* __restrict__ atl)
{
    extern __shared__ char sm[];
    const uint32_t sb = smem_u32(sm);
    const int tid = threadIdx.x;
    const int lane = tid & 31;
    const int w = tid >> 5;
    const int qb = blockIdx.x * 64;
    const int h = blockIdx.y;
    const int b = blockIdx.z;
    const size_t hq = (size_t)h * MROWS + (size_t)b * SEQ;

    const __half* kvsrc[2] = {kf_g, vf_g};

    // Q loads (join first commit group): 2 tiles x 64 rows x 8 chunks
    {
#pragma unroll
        for (int i = 0; i < 8; i++) {
            const int c = tid + i * 128;
            const int t = c >> 9;
            const int r = (c >> 3) & 63;
            const int ch = c & 7;
            const char* src = (const char*)((t ? ql_g : qh_g) + (hq + qb + r) * DH)
                            + ch * 16;
            const uint32_t off = SW128((uint32_t)r * 128 + (uint32_t)ch * 16);
            CP16(sb + t * AQ_TIL + off, src);
        }
    }

    auto load_kv = [&](int it, int st) {
        const int kv = it * 64;
        const uint32_t dst0 = sb + AKV0 + st * AKV_S;
#pragma unroll
        for (int i = 0; i < 8; i++) {
            const int c = tid + i * 128;
            const int t = c >> 9;
            const int r = (c >> 3) & 63;
            const int ch = c & 7;
            const char* src = (const char*)(kvsrc[t] + (hq + kv + r) * DH) + ch * 16;
            const uint32_t off = SW128((uint32_t)r * 128 + (uint32_t)ch * 16);
            CP16(dst0 + t * AKV_T + off, src);
        }
        CP_COMMIT();
    };

    load_kv(0, 0);       // group 0 = Q + kv0
    load_kv(1, 1);       // group 1 = kv1
    CP_WAIT(1);          // Q + kv0 ready
    __syncthreads();

    // hoist Q fragments (reused all 32 iterations)
    uint32_t qfh[4][4], qfl[4][4];
#pragma unroll
    for (int ks = 0; ks < 4; ks++) {
        const int r = w * 16 + (lane & 15);
        const uint32_t off = SW128((uint32_t)r * 128
                            + (uint32_t)(ks * 2 + (lane >> 4)) * 16);
        LDSM4(qfh[ks], sb + off);
        LDSM4(qfl[ks], sb + AQ_TIL + off);
    }

    float o[8][4];
    float m_run[2] = {-1e30f, -1e30f}, l_run[2] = {0.f, 0.f};
#pragma unroll
    for (int nt = 0; nt < 8; nt++)
#pragma unroll
        for (int c = 0; c < 4; c++) o[nt][c] = 0.f;

    int cur = 0, isl = 2;
    for (int it = 0; it < 32; it++) {
        if (it < 30) {
            load_kv(it + 2, isl);
            isl = (isl == 2) ? 0 : isl + 1;
        }
        const uint32_t sK = sb + AKV0 + cur * AKV_S;
        const uint32_t sV = sK + AKV_T;
        cur = (cur == 2) ? 0 : cur + 1;

        // ---- S = Q K^T  (16 q x 64 keys), 2-MMA ----
        float s[8][4];
#pragma unroll
        for (int nt = 0; nt < 8; nt++)
#pragma unroll
            for (int c = 0; c < 4; c++) s[nt][c] = 0.f;

#pragma unroll
        for (int ks = 0; ks < 4; ks++) {
            uint32_t kh_[8][2];
            const int g = lane >> 3;
            const int nr = (lane & 7) + ((g & 2) ? 8 : 0);
            const int cc = ks * 2 + (g & 1);
#pragma unroll
            for (int np = 0; np < 4; np++) {
                const int r = nr + np * 16;
                const uint32_t off = SW128((uint32_t)r * 128 + (uint32_t)cc * 16);
                LDSM4(&kh_[np * 2][0], sK + off);
            }
#pragma unroll
            for (int nt = 0; nt < 8; nt++) {
                MMA_F16(s[nt], qfh[ks], kh_[nt]);
                MMA_F16(s[nt], qfl[ks], kh_[nt]);
            }
        }

        // ---- warp-private online softmax (2 rows per thread) ----
        float corr[2];
#pragma unroll
        for (int hh = 0; hh < 2; hh++) {
            float m = -1e30f;
#pragma unroll
            for (int nt = 0; nt < 8; nt++)
                m = fmaxf(m, fmaxf(s[nt][2 * hh], s[nt][2 * hh + 1]));
            m = fmaxf(m, __shfl_xor_sync(0xffffffffu, m, 1));
            m = fmaxf(m, __shfl_xor_sync(0xffffffffu, m, 2));
            const float mn = fmaxf(m_run[hh], m);
            corr[hh] = __expf(m_run[hh] - mn);
            m_run[hh] = mn;
        }
        float ps[2] = {0.f, 0.f};
#pragma unroll
        for (int nt = 0; nt < 8; nt++)
#pragma unroll
            for (int c = 0; c < 4; c++) {
                const float p = __expf(s[nt][c] - m_run[c >> 1]);
                s[nt][c] = p;
                ps[c >> 1] += p;
            }
#pragma unroll
        for (int hh = 0; hh < 2; hh++) {
            float v = ps[hh];
            v += __shfl_xor_sync(0xffffffffu, v, 1);
            v += __shfl_xor_sync(0xffffffffu, v, 2);
            l_run[hh] = l_run[hh] * corr[hh] + v;
        }
#pragma unroll
        for (int nt = 0; nt < 8; nt++)
#pragma unroll
            for (int c = 0; c < 4; c++) o[nt][c] *= corr[c >> 1];

        // ---- O += P V (register P fp16 hi/lo, ldmatrix.trans V) ----
#pragma unroll
        for (int kc = 0; kc < 4; kc++) {
            uint32_t ph[4], pl[4];
            cvt_hilo16(s[2 * kc][0],     s[2 * kc][1],     ph[0], pl[0]);
            cvt_hilo16(s[2 * kc][2],     s[2 * kc][3],     ph[1], pl[1]);
            cvt_hilo16(s[2 * kc + 1][0], s[2 * kc + 1][1], ph[2], pl[2]);
            cvt_hilo16(s[2 * kc + 1][2], s[2 * kc + 1][3], ph[3], pl[3]);
            uint32_t vh_[8][2];
            const int g = lane >> 3;
            const int kr = kc * 16 + (lane & 7) + ((g & 1) ? 8 : 0);
            const int nf = (g & 2) ? 8 : 0;
#pragma unroll
            for (int np = 0; np < 4; np++) {
                const int cc = np * 2 + (nf >> 3);
                const uint32_t off = SW128((uint32_t)kr * 128 + (uint32_t)cc * 16);
                LDSM4T(&vh_[np * 2][0], sV + off);
            }
#pragma unroll
            for (int nt = 0; nt < 8; nt++) {
                MMA_F16(o[nt], ph, vh_[nt]);
                MMA_F16(o[nt], pl, vh_[nt]);
            }
        }

        if (it < 30) { CP_WAIT(1); } else { CP_WAIT(0); }
        __syncthreads();
    }

    // ---- epilogue: att as fp16 hi/lo, row-major [M][768] ----
#pragma unroll
    for (int hh = 0; hh < 2; hh++) {
        const float inv = 1.f / l_run[hh];
        const size_t m = (size_t)b * SEQ + qb + w * 16 + (lane >> 2) + hh * 8;
#pragma unroll
        for (int nt = 0; nt < 8; nt++) {
            const int col = h * 64 + nt * 8 + (lane & 3) * 2;
            uint32_t hp, lp;
            cvt_hilo16(o[nt][2 * hh] * inv, o[nt][2 * hh + 1] * inv, hp, lp);
            const size_t oi = (m * D_MODEL + col) >> 1;
            ((uint32_t*)ath)[oi] = hp;
            ((uint32_t*)atl)[oi] = lp;
        }
    }
}

// ---------------------------------------------------------------------------
// LayerNorm over last dim (768)
// ---------------------------------------------------------------------------
__global__ __launch_bounds__(256) void ln_kernel(
    const float* __restrict__ x, const float* __restrict__ gamma,
    const float* __restrict__ beta, float* __restrict__ out)
{
    const int row = blockIdx.x;
    const float* xr = x + (size_t)row * D_MODEL;
    const int tid = threadIdx.x;

    float v[3];
    float s = 0.f, s2 = 0.f;
#pragma unroll
    for (int i = 0; i < 3; i++) {
        v[i] = xr[tid + i * 256];
        s += v[i];
        s2 += v[i] * v[i];
    }
#pragma unroll
    for (int off = 16; off; off >>= 1) {
        s  += __shfl_xor_sync(0xffffffffu, s,  off);
        s2 += __shfl_xor_sync(0xffffffffu, s2, off);
    }
    __shared__ float rs[8], rs2[8];
    __shared__ float mu_s, rstd_s;
    const int w = tid >> 5;
    if ((tid & 31) == 0) { rs[w] = s; rs2[w] = s2; }
    __syncthreads();
    if (tid == 0) {
        float a = 0.f, bq = 0.f;
#pragma unroll
        for (int i = 0; i < 8; i++) { a += rs[i]; bq += rs2[i]; }
        float mu = a * (1.f / D_MODEL);
        float var = bq * (1.f / D_MODEL) - mu * mu;
        mu_s = mu;
        rstd_s = rsqrtf(var + 1e-5f);
    }
    __syncthreads();
    const float mu = mu_s, rstd = rstd_s;
#pragma unroll
    for (int i = 0; i < 3; i++) {
        int c = tid + i * 256;
        out[(size_t)row * D_MODEL + c] = (v[i] - mu) * rstd * gamma[c] + beta[c];
    }
}

// ---------------------------------------------------------------------------
// kernel_launch — inputs: Q, W_q, b_q, W_k, b_k, W_v, b_v, W_o, b_o,
//                         ln_gamma, ln_beta
// ---------------------------------------------------------------------------
extern "C" void kernel_launch(void* const* d_in, const int* in_sizes, int n_in,
                              void* d_out, int out_size)
{
    const float* X     = (const float*)d_in[0];
    const float* Wq    = (const float*)d_in[1];
    const float* bq    = (const float*)d_in[2];
    const float* Wk    = (const float*)d_in[3];
    const float* bk    = (const float*)d_in[4];
    const float* Wv    = (const float*)d_in[5];
    const float* bv    = (const float*)d_in[6];
    const float* Wo    = (const float*)d_in[7];
    const float* bo    = (const float*)d_in[8];
    const float* gamma = (const float*)d_in[9];
    const float* beta  = (const float*)d_in[10];
    float* out = (float*)d_out;

    const int M = in_sizes[0] / D_MODEL;   // 4096
    const int B = M / SEQ;                 // 2

    __half *xh, *xl, *wf, *qh, *ql, *kf, *vf, *ath, *atl;
    float* x;
    cudaGetSymbolAddress((void**)&xh, g_xh);  cudaGetSymbolAddress((void**)&xl, g_xl);
    cudaGetSymbolAddress((void**)&wf, g_wf);
    cudaGetSymbolAddress((void**)&qh, g_qh);  cudaGetSymbolAddress((void**)&ql, g_ql);
    cudaGetSymbolAddress((void**)&kf, g_kf);  cudaGetSymbolAddress((void**)&vf, g_vf);
    cudaGetSymbolAddress((void**)&ath, g_ath); cudaGetSymbolAddress((void**)&atl, g_atl);
    cudaGetSymbolAddress((void**)&x, g_x);

    constexpr int G_SMEM_128 = 3 * (2 * G_ATIL + 128 * 64);  // 73728
    constexpr int G_SMEM_64  = 3 * (2 * G_ATIL + 64 * 64);   // 61440

    cudaFuncSetAttribute((const void*)gemm_bs<1, 128>,
                         cudaFuncAttributeMaxDynamicSharedMemorySize, G_SMEM_128);
    cudaFuncSetAttribute((const void*)gemm_bs<0, 64>,
                         cudaFuncAttributeMaxDynamicSharedMemorySize, G_SMEM_64);
    cudaFuncSetAttribute((const void*)attn_bs,
                         cudaFuncAttributeMaxDynamicSharedMemorySize, A_SMEM);

    // 1) one merged split pass
    SplitSrcs ss;
    ss.p[0] = X; ss.p[1] = Wq; ss.p[2] = Wk; ss.p[3] = Wv; ss.p[4] = Wo;
    split_all<<<1184, 256>>>(ss, xh, xl, wf);

    // 2) merged QKV projection (z = 0,1,2) -> head-major fp16
    {
        GemmAux aux;
        aux.bias[0] = bq; aux.bias[1] = bk; aux.bias[2] = bv;
        aux.oh[0] = qh; aux.oh[1] = kf; aux.oh[2] = vf;
        aux.ol = ql;
        aux.R = nullptr; aux.C = nullptr;
        gemm_bs<1, 128><<<dim3(D_MODEL / 128, M / 128, 3), 256, G_SMEM_128>>>(
            xh, xl, wf, aux);
    }

    // 3) attention -> att fp16 hi/lo
    attn_bs<<<dim3(SEQ / 64, NHEADS, B), 128, A_SMEM>>>(qh, ql, kf, vf, ath, atl);

    // 4) O-projection + residual -> fp32 x  (128x64 tiles: 384 CTAs, balanced)
    {
        GemmAux aux;
        aux.bias[0] = bo; aux.bias[1] = bo; aux.bias[2] = bo;
        aux.oh[0] = aux.oh[1] = aux.oh[2] = nullptr;
        aux.ol = nullptr;
        aux.R = X; aux.C = x;
        gemm_bs<0, 64><<<dim3(D_MODEL / 64, M / 128, 1), 256, G_SMEM_64>>>(
            ath, atl, wf + 3 * (size_t)WSZ, aux);
    }

    // 5) LayerNorm
    ln_kernel<<<M, 256>>>(x, gamma, beta, out);
}

// round 12
// speedup vs baseline: 7.8851x; 1.5887x over previous
#include <cuda_runtime.h>
#include <cuda_fp16.h>
#include <cstdint>

// ---------------------------------------------------------------------------
// Problem constants
// ---------------------------------------------------------------------------
#define D_MODEL 768
#define SEQ     2048
#define NHEADS  12
#define DH      64
#define MROWS   (2 * SEQ)
#define WSZ     (D_MODEL * D_MODEL)

// ---------------------------------------------------------------------------
// Global scratch (allocation-free rule). Pure fp16 pipeline: measured output
// dilution (R11: rel_err 2.4e-5 from B-side-only rounding) gives ~10x margin
// for rounding every operand to fp16 and using single MMAs throughout.
// ---------------------------------------------------------------------------
__device__ __half g_xf[MROWS * D_MODEL];
__device__ __half g_wf[4 * WSZ];
// head-major [h][m][64] fp16
__device__ __half g_qf[NHEADS * MROWS * DH];
__device__ __half g_kf[NHEADS * MROWS * DH];
__device__ __half g_vf[NHEADS * MROWS * DH];
__device__ __half g_atf[MROWS * D_MODEL];
__device__ float g_x[MROWS * D_MODEL];

// ---------------------------------------------------------------------------
// PTX helpers
// ---------------------------------------------------------------------------
__device__ __forceinline__ uint32_t smem_u32(const void* p) {
    uint32_t a;
    asm("{ .reg .u64 t; cvta.to.shared.u64 t, %1; cvt.u32.u64 %0, t; }"
        : "=r"(a) : "l"(p));
    return a;
}

#define MMA_F16(d, a, b) \
    asm volatile("mma.sync.aligned.m16n8k16.row.col.f32.f16.f16.f32 " \
        "{%0,%1,%2,%3}, {%4,%5,%6,%7}, {%8,%9}, {%0,%1,%2,%3};" \
        : "+f"((d)[0]), "+f"((d)[1]), "+f"((d)[2]), "+f"((d)[3]) \
        : "r"((a)[0]), "r"((a)[1]), "r"((a)[2]), "r"((a)[3]), \
          "r"((b)[0]), "r"((b)[1]))

#define LDSM4(r, addr) \
    asm volatile("ldmatrix.sync.aligned.m8n8.x4.shared.b16 {%0,%1,%2,%3}, [%4];" \
        : "=r"((r)[0]), "=r"((r)[1]), "=r"((r)[2]), "=r"((r)[3]) : "r"(addr))

#define LDSM4T(r, addr) \
    asm volatile("ldmatrix.sync.aligned.m8n8.x4.trans.shared.b16 {%0,%1,%2,%3}, [%4];" \
        : "=r"((r)[0]), "=r"((r)[1]), "=r"((r)[2]), "=r"((r)[3]) : "r"(addr))

#define CP16(dst, src) \
    asm volatile("cp.async.cg.shared.global [%0], [%1], 16;" \
                 :: "r"(dst), "l"(src))
#define CP_COMMIT() asm volatile("cp.async.commit_group;" ::: "memory")
#define CP_WAIT(N)  asm volatile("cp.async.wait_group %0;" :: "n"(N) : "memory")

// swizzles: rows of 64B (GEMM) and 128B (attention); conflict-free ldmatrix
#define SW64(off)  ((off) ^ (((off) >> 3) & 0x30))
#define SW128(off) ((off) ^ (((off) >> 3) & 0x70))

// pack (x,y) as fp16x2
__device__ __forceinline__ uint32_t cvt_f16x2(float x, float y) {
    __half2 h = __floats2half2_rn(x, y);
    return *(uint32_t*)&h;
}

// ---------------------------------------------------------------------------
// One merged split pass: X and the four weights -> fp16 (rounded)
// ---------------------------------------------------------------------------
struct SplitSrcs { const float* p[5]; };

#define NX4 (MROWS * D_MODEL / 4)   // 786432
#define NW4 (WSZ / 4)               // 147456

__global__ void split_all(SplitSrcs s,
                          __half* __restrict__ xf, __half* __restrict__ wf)
{
    const int total = NX4 + 4 * NW4;
    for (int i = blockIdx.x * blockDim.x + threadIdx.x; i < total;
         i += gridDim.x * blockDim.x) {
        int seg, off;
        if (i < NX4) { seg = 0; off = i; }
        else { const int j = i - NX4; seg = 1 + j / NW4; off = j - (seg - 1) * NW4; }
        const float4 v = ((const float4*)s.p[seg])[off];
        uint32_t* dst = (seg == 0) ? (uint32_t*)xf
                                   : (uint32_t*)(wf + (size_t)(seg - 1) * WSZ);
        dst[2 * off]     = cvt_f16x2(v.x, v.y);
        dst[2 * off + 1] = cvt_f16x2(v.z, v.w);
    }
}

// ---------------------------------------------------------------------------
// GEMM: fp16 x fp16 -> fp32 acc, single MMA.
// CTA tile 128 x NTILE, BK=32, 3-stage cp.async ring (1 sync/iter), 8 warps.
// Swizzled SW64 smem.
// MODE 0 (NTILE=64, 3 CTAs/SM): O-proj -> fp32 C = acc + bias + R
// MODE 1 (NTILE=128, 2 CTAs/SM): QKV -> head-major fp16; z picks W/bias/out
// ---------------------------------------------------------------------------
#define G_ATIL 8192

struct GemmAux {
    const float* bias[3];
    __half* oh[3];
    const float* R;
    float* C;
};

template <int MODE, int NTILE, int OCC>
__global__ __launch_bounds__(256, OCC) void gemm_bs(
    const __half* __restrict__ Ah, const __half* __restrict__ WfB, GemmAux aux)
{
    constexpr int B_TIL = NTILE * 64;
    constexpr int STAGE = G_ATIL + B_TIL;
    constexpr int WN = NTILE / 2;      // per-warp N
    constexpr int NT = WN / 8;         // n-frags per warp
    constexpr int NCHUNK = (128 + NTILE) * 4;  // 16B chunks per stage
    constexpr int PERTHR = NCHUNK / 256;

    extern __shared__ char sm[];
    const uint32_t sb = smem_u32(sm);
    const int tid = threadIdx.x;
    const int lane = tid & 31;
    const int warp = tid >> 5;
    const int wm = warp >> 1;
    const int wn = warp & 1;
    const int bm = blockIdx.y * 128;
    const int bn = blockIdx.x * NTILE;
    const int z = (MODE == 1) ? blockIdx.z : 0;

    const __half* Bf = WfB + (size_t)z * WSZ;
    const float* bias = aux.bias[z];

    auto load_stage = [&](int kt, int st) {
        const uint32_t dst0 = sb + st * STAGE;
#pragma unroll
        for (int i = 0; i < PERTHR; i++) {
            const int c = tid + i * 256;
            int r, toff;
            const __half* base;
            if (c < 512) {                       // A: 512 chunks
                r = c >> 2; toff = 0; base = Ah;
            } else {
                const int j = c - 512;
                r = j >> 2; toff = G_ATIL; base = Bf;
            }
            const int ch = c & 3;
            const int grow = ((c < 512) ? bm : bn) + r;
            const char* src = (const char*)(base + (size_t)grow * D_MODEL + kt * 32)
                            + ch * 16;
            const uint32_t off = (uint32_t)r * 64 + (uint32_t)ch * 16;
            CP16(dst0 + toff + SW64(off), src);
        }
        CP_COMMIT();
    };

    load_stage(0, 0);
    load_stage(1, 1);
    CP_WAIT(1);
    __syncthreads();

    float acc[2][NT][4];
#pragma unroll
    for (int mt = 0; mt < 2; mt++)
#pragma unroll
        for (int nt = 0; nt < NT; nt++)
#pragma unroll
            for (int c = 0; c < 4; c++) acc[mt][nt][c] = 0.f;

    int cur = 0, isl = 2;
    for (int kt = 0; kt < 24; kt++) {
        if (kt < 22) {
            load_stage(kt + 2, isl);
            isl = (isl == 2) ? 0 : isl + 1;
        }
        const uint32_t sA = sb + cur * STAGE;
        cur = (cur == 2) ? 0 : cur + 1;

#pragma unroll
        for (int ks = 0; ks < 2; ks++) {
            uint32_t ah[2][4];
#pragma unroll
            for (int mt = 0; mt < 2; mt++) {
                const int r = wm * 32 + mt * 16 + (lane & 15);
                const uint32_t off = SW64((uint32_t)r * 64
                                    + (uint32_t)(ks * 2 + (lane >> 4)) * 16);
                LDSM4(ah[mt], sA + off);
            }
#pragma unroll
            for (int qg = 0; qg < NT / 4; qg++) {
                uint32_t bh[4][2];
                const int g = lane >> 3;
                const int rb = wn * WN + qg * 32 + (lane & 7) + ((g & 2) ? 8 : 0);
                const int cc = ks * 2 + (g & 1);
#pragma unroll
                for (int np = 0; np < 2; np++) {
                    const int r = rb + np * 16;
                    const uint32_t off = SW64((uint32_t)r * 64 + (uint32_t)cc * 16);
                    LDSM4(&bh[np * 2][0], sA + G_ATIL + off);
                }
#pragma unroll
                for (int mt = 0; mt < 2; mt++)
#pragma unroll
                    for (int n4 = 0; n4 < 4; n4++)
                        MMA_F16(acc[mt][qg * 4 + n4], ah[mt], bh[n4]);
            }
        }
        if (kt < 22) { CP_WAIT(1); } else { CP_WAIT(0); }
        __syncthreads();
    }

    // epilogue
    const float scale = (MODE == 1 && z == 0) ? 0.125f : 1.0f;
#pragma unroll
    for (int mt = 0; mt < 2; mt++)
#pragma unroll
        for (int hh = 0; hh < 2; hh++) {
            const int m = bm + wm * 32 + mt * 16 + (lane >> 2) + hh * 8;
#pragma unroll
            for (int nt = 0; nt < NT; nt++) {
                const int col = bn + wn * WN + nt * 8 + (lane & 3) * 2;
                float x0 = acc[mt][nt][2 * hh]     + bias[col];
                float x1 = acc[mt][nt][2 * hh + 1] + bias[col + 1];
                if (MODE == 0) {
                    const float2 rr = *(const float2*)(aux.R + (size_t)m * D_MODEL + col);
                    float2 v = {x0 + rr.x, x1 + rr.y};
                    *(float2*)(aux.C + (size_t)m * D_MODEL + col) = v;
                } else {
                    const int hd = col >> 6;
                    const int dh = col & 63;
                    const size_t oi = ((size_t)hd * MROWS + m) * 32 + (dh >> 1);
                    ((uint32_t*)aux.oh[z])[oi] = cvt_f16x2(x0 * scale, x1 * scale);
                }
            }
        }
}

// ---------------------------------------------------------------------------
// Flash attention: all operands fp16, single MMA per fragment.
// CTA = 128 threads (4 warps), 64 q rows; warp-private softmax.
// KV tiles of 64 keys, 3-stage cp.async ring, SW128 smem.
// smem: Q 8192 + 3 KV stages x 16384 = 57344 B ; 4 CTAs/SM.
// ---------------------------------------------------------------------------
#define AQ_TIL 8192
#define AKV0   8192
#define AKV_T  8192
#define AKV_S  16384
#define A_SMEM (AKV0 + 3 * AKV_S)   // 57344

__global__ __launch_bounds__(128, 4) void attn_bs(
    const __half* __restrict__ qf_g, const __half* __restrict__ kf_g,
    const __half* __restrict__ vf_g, __half* __restrict__ atf)
{
    extern __shared__ char sm[];
    const uint32_t sb = smem_u32(sm);
    const int tid = threadIdx.x;
    const int lane = tid & 31;
    const int w = tid >> 5;
    const int qb = blockIdx.x * 64;
    const int h = blockIdx.y;
    const int b = blockIdx.z;
    const size_t hq = (size_t)h * MROWS + (size_t)b * SEQ;

    const __half* kvsrc[2] = {kf_g, vf_g};

    // Q loads (join first commit group): 64 rows x 8 chunks = 512
    {
#pragma unroll
        for (int i = 0; i < 4; i++) {
            const int c = tid + i * 128;
            const int r = c >> 3;
            const int ch = c & 7;
            const char* src = (const char*)(qf_g + (hq + qb + r) * DH) + ch * 16;
            const uint32_t off = SW128((uint32_t)r * 128 + (uint32_t)ch * 16);
            CP16(sb + off, src);
        }
    }

    auto load_kv = [&](int it, int st) {
        const int kv = it * 64;
        const uint32_t dst0 = sb + AKV0 + st * AKV_S;
#pragma unroll
        for (int i = 0; i < 8; i++) {
            const int c = tid + i * 128;
            const int t = c >> 9;
            const int r = (c >> 3) & 63;
            const int ch = c & 7;
            const char* src = (const char*)(kvsrc[t] + (hq + kv + r) * DH) + ch * 16;
            const uint32_t off = SW128((uint32_t)r * 128 + (uint32_t)ch * 16);
            CP16(dst0 + t * AKV_T + off, src);
        }
        CP_COMMIT();
    };

    load_kv(0, 0);       // group 0 = Q + kv0
    load_kv(1, 1);       // group 1 = kv1
    CP_WAIT(1);          // Q + kv0 ready
    __syncthreads();

    // hoist Q fragments (reused all 32 iterations)
    uint32_t qf[4][4];
#pragma unroll
    for (int ks = 0; ks < 4; ks++) {
        const int r = w * 16 + (lane & 15);
        const uint32_t off = SW128((uint32_t)r * 128
                            + (uint32_t)(ks * 2 + (lane >> 4)) * 16);
        LDSM4(qf[ks], sb + off);
    }

    float o[8][4];
    float m_run[2] = {-1e30f, -1e30f}, l_run[2] = {0.f, 0.f};
#pragma unroll
    for (int nt = 0; nt < 8; nt++)
#pragma unroll
        for (int c = 0; c < 4; c++) o[nt][c] = 0.f;

    int cur = 0, isl = 2;
    for (int it = 0; it < 32; it++) {
        if (it < 30) {
            load_kv(it + 2, isl);
            isl = (isl == 2) ? 0 : isl + 1;
        }
        const uint32_t sK = sb + AKV0 + cur * AKV_S;
        const uint32_t sV = sK + AKV_T;
        cur = (cur == 2) ? 0 : cur + 1;

        // ---- S = Q K^T  (16 q x 64 keys), single MMA ----
        float s[8][4];
#pragma unroll
        for (int nt = 0; nt < 8; nt++)
#pragma unroll
            for (int c = 0; c < 4; c++) s[nt][c] = 0.f;

#pragma unroll
        for (int ks = 0; ks < 4; ks++) {
            uint32_t kh_[8][2];
            const int g = lane >> 3;
            const int nr = (lane & 7) + ((g & 2) ? 8 : 0);
            const int cc = ks * 2 + (g & 1);
#pragma unroll
            for (int np = 0; np < 4; np++) {
                const int r = nr + np * 16;
                const uint32_t off = SW128((uint32_t)r * 128 + (uint32_t)cc * 16);
                LDSM4(&kh_[np * 2][0], sK + off);
            }
#pragma unroll
            for (int nt = 0; nt < 8; nt++)
                MMA_F16(s[nt], qf[ks], kh_[nt]);
        }

        // ---- warp-private online softmax (2 rows per thread) ----
        float corr[2];
#pragma unroll
        for (int hh = 0; hh < 2; hh++) {
            float m = -1e30f;
#pragma unroll
            for (int nt = 0; nt < 8; nt++)
                m = fmaxf(m, fmaxf(s[nt][2 * hh], s[nt][2 * hh + 1]));
            m = fmaxf(m, __shfl_xor_sync(0xffffffffu, m, 1));
            m = fmaxf(m, __shfl_xor_sync(0xffffffffu, m, 2));
            const float mn = fmaxf(m_run[hh], m);
            corr[hh] = __expf(m_run[hh] - mn);
            m_run[hh] = mn;
        }
        float ps[2] = {0.f, 0.f};
#pragma unroll
        for (int nt = 0; nt < 8; nt++)
#pragma unroll
            for (int c = 0; c < 4; c++) {
                const float p = __expf(s[nt][c] - m_run[c >> 1]);
                s[nt][c] = p;
                ps[c >> 1] += p;
            }
#pragma unroll
        for (int hh = 0; hh < 2; hh++) {
            float v = ps[hh];
            v += __shfl_xor_sync(0xffffffffu, v, 1);
            v += __shfl_xor_sync(0xffffffffu, v, 2);
            l_run[hh] = l_run[hh] * corr[hh] + v;
        }
#pragma unroll
        for (int nt = 0; nt < 8; nt++)
#pragma unroll
            for (int c = 0; c < 4; c++) o[nt][c] *= corr[c >> 1];

        // ---- O += P V (register P fp16, ldmatrix.trans V, single MMA) ----
#pragma unroll
        for (int kc = 0; kc < 4; kc++) {
            uint32_t ph[4];
            ph[0] = cvt_f16x2(s[2 * kc][0],     s[2 * kc][1]);
            ph[1] = cvt_f16x2(s[2 * kc][2],     s[2 * kc][3]);
            ph[2] = cvt_f16x2(s[2 * kc + 1][0], s[2 * kc + 1][1]);
            ph[3] = cvt_f16x2(s[2 * kc + 1][2], s[2 * kc + 1][3]);
            uint32_t vh_[8][2];
            const int g = lane >> 3;
            const int kr = kc * 16 + (lane & 7) + ((g & 1) ? 8 : 0);
            const int nf = (g & 2) ? 8 : 0;
#pragma unroll
            for (int np = 0; np < 4; np++) {
                const int cc = np * 2 + (nf >> 3);
                const uint32_t off = SW128((uint32_t)kr * 128 + (uint32_t)cc * 16);
                LDSM4T(&vh_[np * 2][0], sV + off);
            }
#pragma unroll
            for (int nt = 0; nt < 8; nt++)
                MMA_F16(o[nt], ph, vh_[nt]);
        }

        if (it < 30) { CP_WAIT(1); } else { CP_WAIT(0); }
        __syncthreads();
    }

    // ---- epilogue: att as fp16, row-major [M][768] ----
#pragma unroll
    for (int hh = 0; hh < 2; hh++) {
        const float inv = 1.f / l_run[hh];
        const size_t m = (size_t)b * SEQ + qb + w * 16 + (lane >> 2) + hh * 8;
#pragma unroll
        for (int nt = 0; nt < 8; nt++) {
            const int col = h * 64 + nt * 8 + (lane & 3) * 2;
            const size_t oi = (m * D_MODEL + col) >> 1;
            ((uint32_t*)atf)[oi] =
                cvt_f16x2(o[nt][2 * hh] * inv, o[nt][2 * hh + 1] * inv);
        }
    }
}

// ---------------------------------------------------------------------------
// LayerNorm over last dim (768)
// ---------------------------------------------------------------------------
__global__ __launch_bounds__(256) void ln_kernel(
    const float* __restrict__ x, const float* __restrict__ gamma,
    const float* __restrict__ beta, float* __restrict__ out)
{
    const int row = blockIdx.x;
    const float* xr = x + (size_t)row * D_MODEL;
    const int tid = threadIdx.x;

    float v[3];
    float s = 0.f, s2 = 0.f;
#pragma unroll
    for (int i = 0; i < 3; i++) {
        v[i] = xr[tid + i * 256];
        s += v[i];
        s2 += v[i] * v[i];
    }
#pragma unroll
    for (int off = 16; off; off >>= 1) {
        s  += __shfl_xor_sync(0xffffffffu, s,  off);
        s2 += __shfl_xor_sync(0xffffffffu, s2, off);
    }
    __shared__ float rs[8], rs2[8];
    __shared__ float mu_s, rstd_s;
    const int w = tid >> 5;
    if ((tid & 31) == 0) { rs[w] = s; rs2[w] = s2; }
    __syncthreads();
    if (tid == 0) {
        float a = 0.f, bq = 0.f;
#pragma unroll
        for (int i = 0; i < 8; i++) { a += rs[i]; bq += rs2[i]; }
        float mu = a * (1.f / D_MODEL);
        float var = bq * (1.f / D_MODEL) - mu * mu;
        mu_s = mu;
        rstd_s = rsqrtf(var + 1e-5f);
    }
    __syncthreads();
    const float mu = mu_s, rstd = rstd_s;
#pragma unroll
    for (int i = 0; i < 3; i++) {
        int c = tid + i * 256;
        out[(size_t)row * D_MODEL + c] = (v[i] - mu) * rstd * gamma[c] + beta[c];
    }
}

// ---------------------------------------------------------------------------
// kernel_launch — inputs: Q, W_q, b_q, W_k, b_k, W_v, b_v, W_o, b_o,
//                         ln_gamma, ln_beta
// ---------------------------------------------------------------------------
extern "C" void kernel_launch(void* const* d_in, const int* in_sizes, int n_in,
                              void* d_out, int out_size)
{
    const float* X     = (const float*)d_in[0];
    const float* Wq    = (const float*)d_in[1];
    const float* bq    = (const float*)d_in[2];
    const float* Wk    = (const float*)d_in[3];
    const float* bk    = (const float*)d_in[4];
    const float* Wv    = (const float*)d_in[5];
    const float* bv    = (const float*)d_in[6];
    const float* Wo    = (const float*)d_in[7];
    const float* bo    = (const float*)d_in[8];
    const float* gamma = (const float*)d_in[9];
    const float* beta  = (const float*)d_in[10];
    float* out = (float*)d_out;

    const int M = in_sizes[0] / D_MODEL;   // 4096
    const int B = M / SEQ;                 // 2

    __half *xf, *wf, *qf, *kf, *vf, *atf;
    float* x;
    cudaGetSymbolAddress((void**)&xf, g_xf);
    cudaGetSymbolAddress((void**)&wf, g_wf);
    cudaGetSymbolAddress((void**)&qf, g_qf);
    cudaGetSymbolAddress((void**)&kf, g_kf);
    cudaGetSymbolAddress((void**)&vf, g_vf);
    cudaGetSymbolAddress((void**)&atf, g_atf);
    cudaGetSymbolAddress((void**)&x, g_x);

    constexpr int G_SMEM_128 = 3 * (G_ATIL + 128 * 64);  // 49152
    constexpr int G_SMEM_64  = 3 * (G_ATIL + 64 * 64);   // 36864

    cudaFuncSetAttribute((const void*)gemm_bs<1, 128, 2>,
                         cudaFuncAttributeMaxDynamicSharedMemorySize, G_SMEM_128);
    cudaFuncSetAttribute((const void*)gemm_bs<0, 64, 3>,
                         cudaFuncAttributeMaxDynamicSharedMemorySize, G_SMEM_64);
    cudaFuncSetAttribute((const void*)attn_bs,
                         cudaFuncAttributeMaxDynamicSharedMemorySize, A_SMEM);

    // 1) one merged split pass (fp16 round)
    SplitSrcs ss;
    ss.p[0] = X; ss.p[1] = Wq; ss.p[2] = Wk; ss.p[3] = Wv; ss.p[4] = Wo;
    split_all<<<1184, 256>>>(ss, xf, wf);

    // 2) merged QKV projection (z = 0,1,2) -> head-major fp16
    {
        GemmAux aux;
        aux.bias[0] = bq; aux.bias[1] = bk; aux.bias[2] = bv;
        aux.oh[0] = qf; aux.oh[1] = kf; aux.oh[2] = vf;
        aux.R = nullptr; aux.C = nullptr;
        gemm_bs<1, 128, 2><<<dim3(D_MODEL / 128, M / 128, 3), 256, G_SMEM_128>>>(
            xf, wf, aux);
    }

    // 3) attention -> att fp16
    attn_bs<<<dim3(SEQ / 64, NHEADS, B), 128, A_SMEM>>>(qf, kf, vf, atf);

    // 4) O-projection + residual -> fp32 x (128x64 tiles: 384 CTAs, 1 wave @3/SM)
    {
        GemmAux aux;
        aux.bias[0] = bo; aux.bias[1] = bo; aux.bias[2] = bo;
        aux.oh[0] = aux.oh[1] = aux.oh[2] = nullptr;
        aux.R = X; aux.C = x;
        gemm_bs<0, 64, 3><<<dim3(D_MODEL / 64, M / 128, 1), 256, G_SMEM_64>>>(
            atf, wf + 3 * (size_t)WSZ, aux);
    }

    // 5) LayerNorm
    ln_kernel<<<M, 256>>>(x, gamma, beta, out);
}

// round 13
// speedup vs baseline: 8.3982x; 1.0651x over previous
#include <cuda_runtime.h>
#include <cuda_fp16.h>
#include <cstdint>

// ---------------------------------------------------------------------------
// Problem constants
// ---------------------------------------------------------------------------
#define D_MODEL 768
#define SEQ     2048
#define NHEADS  12
#define DH      64
#define MROWS   (2 * SEQ)
#define WSZ     (D_MODEL * D_MODEL)

// ---------------------------------------------------------------------------
// Global scratch (allocation-free rule). Pure fp16 operands (measured R12:
// rel_err 3.3e-5, 30x under threshold).
// ---------------------------------------------------------------------------
__device__ __half g_xf[MROWS * D_MODEL];
__device__ __half g_wf[4 * WSZ];
// head-major [h][m][64] fp16
__device__ __half g_qf[NHEADS * MROWS * DH];
__device__ __half g_kf[NHEADS * MROWS * DH];
__device__ __half g_vf[NHEADS * MROWS * DH];
__device__ __half g_atf[MROWS * D_MODEL];
__device__ float g_x[MROWS * D_MODEL];

// ---------------------------------------------------------------------------
// PTX helpers
// ---------------------------------------------------------------------------
__device__ __forceinline__ uint32_t smem_u32(const void* p) {
    uint32_t a;
    asm("{ .reg .u64 t; cvta.to.shared.u64 t, %1; cvt.u32.u64 %0, t; }"
        : "=r"(a) : "l"(p));
    return a;
}

#define MMA_F16(d, a, b) \
    asm volatile("mma.sync.aligned.m16n8k16.row.col.f32.f16.f16.f32 " \
        "{%0,%1,%2,%3}, {%4,%5,%6,%7}, {%8,%9}, {%0,%1,%2,%3};" \
        : "+f"((d)[0]), "+f"((d)[1]), "+f"((d)[2]), "+f"((d)[3]) \
        : "r"((a)[0]), "r"((a)[1]), "r"((a)[2]), "r"((a)[3]), \
          "r"((b)[0]), "r"((b)[1]))

#define LDSM4(r, addr) \
    asm volatile("ldmatrix.sync.aligned.m8n8.x4.shared.b16 {%0,%1,%2,%3}, [%4];" \
        : "=r"((r)[0]), "=r"((r)[1]), "=r"((r)[2]), "=r"((r)[3]) : "r"(addr))

#define LDSM4T(r, addr) \
    asm volatile("ldmatrix.sync.aligned.m8n8.x4.trans.shared.b16 {%0,%1,%2,%3}, [%4];" \
        : "=r"((r)[0]), "=r"((r)[1]), "=r"((r)[2]), "=r"((r)[3]) : "r"(addr))

#define CP16(dst, src) \
    asm volatile("cp.async.cg.shared.global [%0], [%1], 16;" \
                 :: "r"(dst), "l"(src))
#define CP_COMMIT() asm volatile("cp.async.commit_group;" ::: "memory")
#define CP_WAIT(N)  asm volatile("cp.async.wait_group %0;" :: "n"(N) : "memory")

// SW128 swizzle: rows of 128B; conflict-free ldmatrix
#define SW128(off) ((off) ^ (((off) >> 3) & 0x70))

// pack (x,y) as fp16x2
__device__ __forceinline__ uint32_t cvt_f16x2(float x, float y) {
    __half2 h = __floats2half2_rn(x, y);
    return *(uint32_t*)&h;
}

// ---------------------------------------------------------------------------
// One merged split pass: X and the four weights -> fp16 (rounded)
// ---------------------------------------------------------------------------
struct SplitSrcs { const float* p[5]; };

#define NX4 (MROWS * D_MODEL / 4)   // 786432
#define NW4 (WSZ / 4)               // 147456

__global__ void split_all(SplitSrcs s,
                          __half* __restrict__ xf, __half* __restrict__ wf)
{
    const int total = NX4 + 4 * NW4;
    for (int i = blockIdx.x * blockDim.x + threadIdx.x; i < total;
         i += gridDim.x * blockDim.x) {
        int seg, off;
        if (i < NX4) { seg = 0; off = i; }
        else { const int j = i - NX4; seg = 1 + j / NW4; off = j - (seg - 1) * NW4; }
        const float4 v = ((const float4*)s.p[seg])[off];
        uint32_t* dst = (seg == 0) ? (uint32_t*)xf
                                   : (uint32_t*)(wf + (size_t)(seg - 1) * WSZ);
        dst[2 * off]     = cvt_f16x2(v.x, v.y);
        dst[2 * off + 1] = cvt_f16x2(v.z, v.w);
    }
}

// ---------------------------------------------------------------------------
// GEMM: fp16 x fp16 -> fp32 acc, single MMA.
// CTA tile 128 x NTILE, BK=64 (128B rows, SW128), 3-stage cp.async ring
// (1 sync/iter), 12 k-iters, 8 warps.
// MODE 0 (NTILE=64, 3 CTAs/SM): O-proj -> fp32 C = acc + bias + R
// MODE 1 (NTILE=128, 2 CTAs/SM): QKV -> head-major fp16; z picks W/bias/out
// ---------------------------------------------------------------------------
#define G_ATIL 16384

struct GemmAux {
    const float* bias[3];
    __half* oh[3];
    const float* R;
    float* C;
};

template <int MODE, int NTILE, int OCC>
__global__ __launch_bounds__(256, OCC) void gemm_bs(
    const __half* __restrict__ Ah, const __half* __restrict__ WfB, GemmAux aux)
{
    constexpr int B_TIL = NTILE * 128;
    constexpr int STAGE = G_ATIL + B_TIL;
    constexpr int WN = NTILE / 2;      // per-warp N
    constexpr int NT = WN / 8;         // n-frags per warp
    constexpr int NCHUNK = (128 + NTILE) * 8;  // 16B chunks per stage
    constexpr int PERTHR = NCHUNK / 256;

    extern __shared__ char sm[];
    const uint32_t sb = smem_u32(sm);
    const int tid = threadIdx.x;
    const int lane = tid & 31;
    const int warp = tid >> 5;
    const int wm = warp >> 1;
    const int wn = warp & 1;
    const int bm = blockIdx.y * 128;
    const int bn = blockIdx.x * NTILE;
    const int z = (MODE == 1) ? blockIdx.z : 0;

    const __half* Bf = WfB + (size_t)z * WSZ;
    const float* bias = aux.bias[z];

    auto load_stage = [&](int kt, int st) {
        const uint32_t dst0 = sb + st * STAGE;
#pragma unroll
        for (int i = 0; i < PERTHR; i++) {
            const int c = tid + i * 256;
            int r, toff;
            const __half* base;
            if (c < 1024) {                      // A: 1024 chunks
                r = c >> 3; toff = 0; base = Ah;
            } else {
                const int j = c - 1024;
                r = j >> 3; toff = G_ATIL; base = Bf;
            }
            const int ch = c & 7;
            const int grow = ((c < 1024) ? bm : bn) + r;
            const char* src = (const char*)(base + (size_t)grow * D_MODEL + kt * 64)
                            + ch * 16;
            const uint32_t off = SW128((uint32_t)r * 128 + (uint32_t)ch * 16);
            CP16(dst0 + toff + off, src);
        }
        CP_COMMIT();
    };

    load_stage(0, 0);
    load_stage(1, 1);
    CP_WAIT(1);
    __syncthreads();

    float acc[2][NT][4];
#pragma unroll
    for (int mt = 0; mt < 2; mt++)
#pragma unroll
        for (int nt = 0; nt < NT; nt++)
#pragma unroll
            for (int c = 0; c < 4; c++) acc[mt][nt][c] = 0.f;

    int cur = 0, isl = 2;
    for (int kt = 0; kt < 12; kt++) {
        if (kt < 10) {
            load_stage(kt + 2, isl);
            isl = (isl == 2) ? 0 : isl + 1;
        }
        const uint32_t sA = sb + cur * STAGE;
        cur = (cur == 2) ? 0 : cur + 1;

#pragma unroll
        for (int ks = 0; ks < 4; ks++) {
            uint32_t ah[2][4];
#pragma unroll
            for (int mt = 0; mt < 2; mt++) {
                const int r = wm * 32 + mt * 16 + (lane & 15);
                const uint32_t off = SW128((uint32_t)r * 128
                                    + (uint32_t)(ks * 2 + (lane >> 4)) * 16);
                LDSM4(ah[mt], sA + off);
            }
#pragma unroll
            for (int qg = 0; qg < NT / 4; qg++) {
                uint32_t bh[4][2];
                const int g = lane >> 3;
                const int rb = wn * WN + qg * 32 + (lane & 7) + ((g & 2) ? 8 : 0);
                const int cc = ks * 2 + (g & 1);
#pragma unroll
                for (int np = 0; np < 2; np++) {
                    const int r = rb + np * 16;
                    const uint32_t off = SW128((uint32_t)r * 128 + (uint32_t)cc * 16);
                    LDSM4(&bh[np * 2][0], sA + G_ATIL + off);
                }
#pragma unroll
                for (int mt = 0; mt < 2; mt++)
#pragma unroll
                    for (int n4 = 0; n4 < 4; n4++)
                        MMA_F16(acc[mt][qg * 4 + n4], ah[mt], bh[n4]);
            }
        }
        if (kt < 10) { CP_WAIT(1); } else { CP_WAIT(0); }
        __syncthreads();
    }

    // epilogue (Q scale folds 1/sqrt(dh) and log2e for exp2 softmax)
    const float scale = (MODE == 1 && z == 0) ? 0.125f * 1.44269504089f : 1.0f;
#pragma unroll
    for (int mt = 0; mt < 2; mt++)
#pragma unroll
        for (int hh = 0; hh < 2; hh++) {
            const int m = bm + wm * 32 + mt * 16 + (lane >> 2) + hh * 8;
#pragma unroll
            for (int nt = 0; nt < NT; nt++) {
                const int col = bn + wn * WN + nt * 8 + (lane & 3) * 2;
                float x0 = acc[mt][nt][2 * hh]     + bias[col];
                float x1 = acc[mt][nt][2 * hh + 1] + bias[col + 1];
                if (MODE == 0) {
                    const float2 rr = *(const float2*)(aux.R + (size_t)m * D_MODEL + col);
                    float2 v = {x0 + rr.x, x1 + rr.y};
                    *(float2*)(aux.C + (size_t)m * D_MODEL + col) = v;
                } else {
                    const int hd = col >> 6;
                    const int dh = col & 63;
                    const size_t oi = ((size_t)hd * MROWS + m) * 32 + (dh >> 1);
                    ((uint32_t*)aux.oh[z])[oi] = cvt_f16x2(x0 * scale, x1 * scale);
                }
            }
        }
}

// ---------------------------------------------------------------------------
// Flash attention: fp16 operands, single MMA; Q pre-scaled by log2e/8 so
// softmax uses exp2f. CTA = 128 threads (4 warps), 64 q rows.
// KV tiles of 128 keys (one softmax round per 128 keys), 2-stage ring,
// 16 iterations. smem: Q 8192 + 2 x 32768 = 73728 B ; 3 CTAs/SM.
// ---------------------------------------------------------------------------
#define AQ_TIL 8192
#define AKV0   8192
#define AKV_T  16384
#define AKV_S  32768
#define A_SMEM (AKV0 + 2 * AKV_S)   // 73728

__global__ __launch_bounds__(128, 3) void attn_bs(
    const __half* __restrict__ qf_g, const __half* __restrict__ kf_g,
    const __half* __restrict__ vf_g, __half* __restrict__ atf)
{
    extern __shared__ char sm[];
    const uint32_t sb = smem_u32(sm);
    const int tid = threadIdx.x;
    const int lane = tid & 31;
    const int w = tid >> 5;
    const int qb = blockIdx.x * 64;
    const int h = blockIdx.y;
    const int b = blockIdx.z;
    const size_t hq = (size_t)h * MROWS + (size_t)b * SEQ;

    const __half* kvsrc[2] = {kf_g, vf_g};

    // Q loads (join first commit group): 64 rows x 8 chunks = 512
    {
#pragma unroll
        for (int i = 0; i < 4; i++) {
            const int c = tid + i * 128;
            const int r = c >> 3;
            const int ch = c & 7;
            const char* src = (const char*)(qf_g + (hq + qb + r) * DH) + ch * 16;
            const uint32_t off = SW128((uint32_t)r * 128 + (uint32_t)ch * 16);
            CP16(sb + off, src);
        }
    }

    // KV tile of 128 keys: 2 tiles x 128 rows x 8 chunks = 2048 -> 16/thread
    auto load_kv = [&](int it, int st) {
        const int kv = it * 128;
        const uint32_t dst0 = sb + AKV0 + st * AKV_S;
#pragma unroll
        for (int i = 0; i < 16; i++) {
            const int c = tid + i * 128;
            const int t = c >> 10;
            const int r = (c >> 3) & 127;
            const int ch = c & 7;
            const char* src = (const char*)(kvsrc[t] + (hq + kv + r) * DH) + ch * 16;
            const uint32_t off = SW128((uint32_t)r * 128 + (uint32_t)ch * 16);
            CP16(dst0 + t * AKV_T + off, src);
        }
        CP_COMMIT();
    };

    load_kv(0, 0);       // group 0 = Q + kv0
    load_kv(1, 1);       // group 1 = kv1
    CP_WAIT(1);          // Q + kv0 ready
    __syncthreads();

    // hoist Q fragments (reused all 16 iterations)
    uint32_t qf[4][4];
#pragma unroll
    for (int ks = 0; ks < 4; ks++) {
        const int r = w * 16 + (lane & 15);
        const uint32_t off = SW128((uint32_t)r * 128
                            + (uint32_t)(ks * 2 + (lane >> 4)) * 16);
        LDSM4(qf[ks], sb + off);
    }

    float o[8][4];
    float m_run[2] = {-1e30f, -1e30f}, l_run[2] = {0.f, 0.f};
#pragma unroll
    for (int nt = 0; nt < 8; nt++)
#pragma unroll
        for (int c = 0; c < 4; c++) o[nt][c] = 0.f;

    for (int it = 0; it < 16; it++) {
        const uint32_t sK = sb + AKV0 + (it & 1) * AKV_S;
        const uint32_t sV = sK + AKV_T;

        // ---- S = Q K^T  (16 q x 128 keys) ----
        float s[16][4];
#pragma unroll
        for (int nt = 0; nt < 16; nt++)
#pragma unroll
            for (int c = 0; c < 4; c++) s[nt][c] = 0.f;

#pragma unroll
        for (int ks = 0; ks < 4; ks++) {
            uint32_t kh_[16][2];
            const int g = lane >> 3;
            const int nr = (lane & 7) + ((g & 2) ? 8 : 0);
            const int cc = ks * 2 + (g & 1);
#pragma unroll
            for (int np = 0; np < 8; np++) {
                const int r = nr + np * 16;
                const uint32_t off = SW128((uint32_t)r * 128 + (uint32_t)cc * 16);
                LDSM4(&kh_[np * 2][0], sK + off);
            }
#pragma unroll
            for (int nt = 0; nt < 16; nt++)
                MMA_F16(s[nt], qf[ks], kh_[nt]);
        }

        // ---- warp-private online softmax over 128 keys (base-2) ----
        float corr[2];
#pragma unroll
        for (int hh = 0; hh < 2; hh++) {
            float m = -1e30f;
#pragma unroll
            for (int nt = 0; nt < 16; nt++)
                m = fmaxf(m, fmaxf(s[nt][2 * hh], s[nt][2 * hh + 1]));
            m = fmaxf(m, __shfl_xor_sync(0xffffffffu, m, 1));
            m = fmaxf(m, __shfl_xor_sync(0xffffffffu, m, 2));
            const float mn = fmaxf(m_run[hh], m);
            corr[hh] = exp2f(m_run[hh] - mn);
            m_run[hh] = mn;
        }
        float ps[2] = {0.f, 0.f};
#pragma unroll
        for (int nt = 0; nt < 16; nt++)
#pragma unroll
            for (int c = 0; c < 4; c++) {
                const float p = exp2f(s[nt][c] - m_run[c >> 1]);
                s[nt][c] = p;
                ps[c >> 1] += p;
            }
#pragma unroll
        for (int hh = 0; hh < 2; hh++) {
            float v = ps[hh];
            v += __shfl_xor_sync(0xffffffffu, v, 1);
            v += __shfl_xor_sync(0xffffffffu, v, 2);
            l_run[hh] = l_run[hh] * corr[hh] + v;
        }
#pragma unroll
        for (int nt = 0; nt < 8; nt++)
#pragma unroll
            for (int c = 0; c < 4; c++) o[nt][c] *= corr[c >> 1];

        // ---- O += P V (register P fp16, ldmatrix.trans V) ----
#pragma unroll
        for (int kc = 0; kc < 8; kc++) {
            uint32_t ph[4];
            ph[0] = cvt_f16x2(s[2 * kc][0],     s[2 * kc][1]);
            ph[1] = cvt_f16x2(s[2 * kc][2],     s[2 * kc][3]);
            ph[2] = cvt_f16x2(s[2 * kc + 1][0], s[2 * kc + 1][1]);
            ph[3] = cvt_f16x2(s[2 * kc + 1][2], s[2 * kc + 1][3]);
            uint32_t vh_[8][2];
            const int g = lane >> 3;
            const int kr = kc * 16 + (lane & 7) + ((g & 1) ? 8 : 0);
            const int nf = (g & 2) ? 8 : 0;
#pragma unroll
            for (int np = 0; np < 4; np++) {
                const int cc = np * 2 + (nf >> 3);
                const uint32_t off = SW128((uint32_t)kr * 128 + (uint32_t)cc * 16);
                LDSM4T(&vh_[np * 2][0], sV + off);
            }
#pragma unroll
            for (int nt = 0; nt < 8; nt++)
                MMA_F16(o[nt], ph, vh_[nt]);
        }

        __syncthreads();                 // done reading this stage
        if (it < 14) {
            load_kv(it + 2, it & 1);     // refill freed stage
            CP_WAIT(1);
        } else {
            CP_WAIT(0);
        }
        __syncthreads();
    }

    // ---- epilogue: att as fp16, row-major [M][768] ----
#pragma unroll
    for (int hh = 0; hh < 2; hh++) {
        const float inv = 1.f / l_run[hh];
        const size_t m = (size_t)b * SEQ + qb + w * 16 + (lane >> 2) + hh * 8;
#pragma unroll
        for (int nt = 0; nt < 8; nt++) {
            const int col = h * 64 + nt * 8 + (lane & 3) * 2;
            const size_t oi = (m * D_MODEL + col) >> 1;
            ((uint32_t*)atf)[oi] =
                cvt_f16x2(o[nt][2 * hh] * inv, o[nt][2 * hh + 1] * inv);
        }
    }
}

// ---------------------------------------------------------------------------
// LayerNorm over last dim (768)
// ---------------------------------------------------------------------------
__global__ __launch_bounds__(256) void ln_kernel(
    const float* __restrict__ x, const float* __restrict__ gamma,
    const float* __restrict__ beta, float* __restrict__ out)
{
    const int row = blockIdx.x;
    const float* xr = x + (size_t)row * D_MODEL;
    const int tid = threadIdx.x;

    float v[3];
    float s = 0.f, s2 = 0.f;
#pragma unroll
    for (int i = 0; i < 3; i++) {
        v[i] = xr[tid + i * 256];
        s += v[i];
        s2 += v[i] * v[i];
    }
#pragma unroll
    for (int off = 16; off; off >>= 1) {
        s  += __shfl_xor_sync(0xffffffffu, s,  off);
        s2 += __shfl_xor_sync(0xffffffffu, s2, off);
    }
    __shared__ float rs[8], rs2[8];
    __shared__ float mu_s, rstd_s;
    const int w = tid >> 5;
    if ((tid & 31) == 0) { rs[w] = s; rs2[w] = s2; }
    __syncthreads();
    if (tid == 0) {
        float a = 0.f, bq = 0.f;
#pragma unroll
        for (int i = 0; i < 8; i++) { a += rs[i]; bq += rs2[i]; }
        float mu = a * (1.f / D_MODEL);
        float var = bq * (1.f / D_MODEL) - mu * mu;
        mu_s = mu;
        rstd_s = rsqrtf(var + 1e-5f);
    }
    __syncthreads();
    const float mu = mu_s, rstd = rstd_s;
#pragma unroll
    for (int i = 0; i < 3; i++) {
        int c = tid + i * 256;
        out[(size_t)row * D_MODEL + c] = (v[i] - mu) * rstd * gamma[c] + beta[c];
    }
}

// ---------------------------------------------------------------------------
// kernel_launch — inputs: Q, W_q, b_q, W_k, b_k, W_v, b_v, W_o, b_o,
//                         ln_gamma, ln_beta
// ---------------------------------------------------------------------------
extern "C" void kernel_launch(void* const* d_in, const int* in_sizes, int n_in,
                              void* d_out, int out_size)
{
    const float* X     = (const float*)d_in[0];
    const float* Wq    = (const float*)d_in[1];
    const float* bq    = (const float*)d_in[2];
    const float* Wk    = (const float*)d_in[3];
    const float* bk    = (const float*)d_in[4];
    const float* Wv    = (const float*)d_in[5];
    const float* bv    = (const float*)d_in[6];
    const float* Wo    = (const float*)d_in[7];
    const float* bo    = (const float*)d_in[8];
    const float* gamma = (const float*)d_in[9];
    const float* beta  = (const float*)d_in[10];
    float* out = (float*)d_out;

    const int M = in_sizes[0] / D_MODEL;   // 4096
    const int B = M / SEQ;                 // 2

    __half *xf, *wf, *qf, *kf, *vf, *atf;
    float* x;
    cudaGetSymbolAddress((void**)&xf, g_xf);
    cudaGetSymbolAddress((void**)&wf, g_wf);
    cudaGetSymbolAddress((void**)&qf, g_qf);
    cudaGetSymbolAddress((void**)&kf, g_kf);
    cudaGetSymbolAddress((void**)&vf, g_vf);
    cudaGetSymbolAddress((void**)&atf, g_atf);
    cudaGetSymbolAddress((void**)&x, g_x);

    constexpr int G_SMEM_128 = 3 * (G_ATIL + 128 * 128);  // 98304
    constexpr int G_SMEM_64  = 3 * (G_ATIL + 64 * 128);   // 73728

    cudaFuncSetAttribute((const void*)gemm_bs<1, 128, 2>,
                         cudaFuncAttributeMaxDynamicSharedMemorySize, G_SMEM_128);
    cudaFuncSetAttribute((const void*)gemm_bs<0, 64, 3>,
                         cudaFuncAttributeMaxDynamicSharedMemorySize, G_SMEM_64);
    cudaFuncSetAttribute((const void*)attn_bs,
                         cudaFuncAttributeMaxDynamicSharedMemorySize, A_SMEM);

    // 1) one merged split pass (fp16 round)
    SplitSrcs ss;
    ss.p[0] = X; ss.p[1] = Wq; ss.p[2] = Wk; ss.p[3] = Wv; ss.p[4] = Wo;
    split_all<<<1184, 256>>>(ss, xf, wf);

    // 2) merged QKV projection (z = 0,1,2) -> head-major fp16
    {
        GemmAux aux;
        aux.bias[0] = bq; aux.bias[1] = bk; aux.bias[2] = bv;
        aux.oh[0] = qf; aux.oh[1] = kf; aux.oh[2] = vf;
        aux.R = nullptr; aux.C = nullptr;
        gemm_bs<1, 128, 2><<<dim3(D_MODEL / 128, M / 128, 3), 256, G_SMEM_128>>>(
            xf, wf, aux);
    }

    // 3) attention -> att fp16
    attn_bs<<<dim3(SEQ / 64, NHEADS, B), 128, A_SMEM>>>(qf, kf, vf, atf);

    // 4) O-projection + residual -> fp32 x (128x64 tiles, 3 CTAs/SM)
    {
        GemmAux aux;
        aux.bias[0] = bo; aux.bias[1] = bo; aux.bias[2] = bo;
        aux.oh[0] = aux.oh[1] = aux.oh[2] = nullptr;
        aux.R = X; aux.C = x;
        gemm_bs<0, 64, 3><<<dim3(D_MODEL / 64, M / 128, 1), 256, G_SMEM_64>>>(
            atf, wf + 3 * (size_t)WSZ, aux);
    }

    // 5) LayerNorm
    ln_kernel<<<M, 256>>>(x, gamma, beta, out);
}